// round 1
// baseline (speedup 1.0000x reference)
#include <cuda_runtime.h>
#include <math.h>

#define Bn   2
#define Tn   2048
#define Cn   768
#define Hn   12
#define HDn  64
#define QKVn 2304
#define SCALE 0.125f   // 1/sqrt(64)

// -------- device scratch (no allocations allowed) --------
__device__ float g_qkv[Bn * Tn * QKVn];   // qkv = x@w_attn^T + b   [B*T, 2304]
__device__ float g_qs [Bn * Tn * Cn];     // sel_w-scaled concat-q  [B*T, 768]
__device__ float g_ff [Bn * Tn * Tn];     // S, then exclusive cumsum (FF_shifted)
__device__ float g_y  [Bn * Tn * Cn];     // attention output       [B*T, 768]

// ============================================================================
// Generic NT SGEMM: C[m,n] = sum_k A[m,k]*B[n,k]  (both operands K-major)
// 128x128 tile, BK=8, 256 threads, 8x8 microtile.
// MODE 0: qkv epilogue (bias + scatter scaled q into g_qs)
// MODE 1: selection S epilogue (scale, causal/diag/col0 mask, relu) + causal skip
// MODE 2: proj epilogue (bias)
// ============================================================================
template <int MODE>
__global__ void __launch_bounds__(256)
sgemm_nt(const float* __restrict__ A, int lda, long sA,
         const float* __restrict__ Bm, int ldb, long sB,
         float* __restrict__ C, int ldc, long sC,
         int K,
         const float* __restrict__ bias,
         const float* __restrict__ selw)
{
    const int bx = blockIdx.x, by = blockIdx.y, bz = blockIdx.z;
    const int i0 = by * 128, j0 = bx * 128;
    if (MODE == 1 && j0 >= i0 + 128) return;   // strictly-upper tile: skip

    A  += (long)bz * sA;
    Bm += (long)bz * sB;
    C  += (long)bz * sC;

    __shared__ float As[8][132];
    __shared__ float Bs[8][132];

    const int tid = threadIdx.x;
    const int tx = tid & 15, ty = tid >> 4;
    const int lr = tid >> 1;          // load row 0..127
    const int lk = (tid & 1) * 4;     // k sub-offset 0 or 4

    float acc[8][8];
    #pragma unroll
    for (int a = 0; a < 8; a++)
        #pragma unroll
        for (int b = 0; b < 8; b++) acc[a][b] = 0.f;

    for (int k0 = 0; k0 < K; k0 += 8) {
        float4 av = *(const float4*)(A  + (long)(i0 + lr) * lda + k0 + lk);
        float4 bv = *(const float4*)(Bm + (long)(j0 + lr) * ldb + k0 + lk);
        As[lk + 0][lr] = av.x; As[lk + 1][lr] = av.y;
        As[lk + 2][lr] = av.z; As[lk + 3][lr] = av.w;
        Bs[lk + 0][lr] = bv.x; Bs[lk + 1][lr] = bv.y;
        Bs[lk + 2][lr] = bv.z; Bs[lk + 3][lr] = bv.w;
        __syncthreads();

        #pragma unroll
        for (int kk = 0; kk < 8; kk++) {
            float a[8], b[8];
            #pragma unroll
            for (int u = 0; u < 2; u++) {
                float4 v = *(const float4*)&As[kk][ty * 8 + u * 4];
                a[u*4+0] = v.x; a[u*4+1] = v.y; a[u*4+2] = v.z; a[u*4+3] = v.w;
                float4 w = *(const float4*)&Bs[kk][tx * 8 + u * 4];
                b[u*4+0] = w.x; b[u*4+1] = w.y; b[u*4+2] = w.z; b[u*4+3] = w.w;
            }
            #pragma unroll
            for (int ii = 0; ii < 8; ii++)
                #pragma unroll
                for (int jj = 0; jj < 8; jj++)
                    acc[ii][jj] += a[ii] * b[jj];
        }
        __syncthreads();
    }

    if (MODE == 0) {
        #pragma unroll
        for (int ii = 0; ii < 8; ii++) {
            const int m = i0 + ty * 8 + ii;
            #pragma unroll
            for (int jj = 0; jj < 8; jj++) {
                const int n = j0 + tx * 8 + jj;
                const float v = acc[ii][jj] + bias[n];
                C[(long)m * ldc + n] = v;
                if (n < Cn)   // q slice -> sel_w-scaled concat-q for S GEMM
                    g_qs[(long)m * Cn + n] = v * selw[n >> 6];
            }
        }
    } else if (MODE == 1) {
        #pragma unroll
        for (int ii = 0; ii < 8; ii++) {
            const int i = i0 + ty * 8 + ii;
            #pragma unroll
            for (int jj = 0; jj < 8; jj++) {
                const int j = j0 + tx * 8 + jj;
                float v = acc[ii][jj] * SCALE;
                v = (j >= 1 && j < i) ? fmaxf(v, 0.f) : 0.f;
                C[(long)i * ldc + j] = v;
            }
        }
    } else {
        #pragma unroll
        for (int ii = 0; ii < 8; ii++) {
            const int m = i0 + ty * 8 + ii;
            #pragma unroll
            for (int jj = 0; jj < 8; jj++) {
                const int n = j0 + tx * 8 + jj;
                C[(long)m * ldc + n] = acc[ii][jj] + bias[n];
            }
        }
    }
}

// ============================================================================
// In-place exclusive cumsum of S over rows i (per batch, per column j).
// Gated on i > j so garbage in never-written upper-triangle tiles is ignored.
// ============================================================================
__global__ void cumsum_kernel()
{
    const int g = blockIdx.x * blockDim.x + threadIdx.x;  // 0 .. B*T-1
    const int b = g >> 11;
    const int j = g & 2047;
    float* col = g_ff + (long)b * Tn * Tn + j;
    float acc = 0.f;
    #pragma unroll 4
    for (int i = 0; i < Tn; i++) {
        const float s = col[i * Tn];
        col[i * Tn] = acc;             // exclusive prefix (FF_shifted)
        if (i > j) acc += s;
    }
}

// ============================================================================
// Attention: per (b,h), 128 query rows per block, thread-per-row.
// logits = q.k*scale - FF_shifted[i,j]; online softmax; o = sum p*v.
// K/V tiles (32x64) + FF tile (128x32, padded) staged in smem.
// ============================================================================
__global__ void __launch_bounds__(128) attn_kernel()
{
    const int bx = blockIdx.x;         // query tile 0..15
    const int bh = blockIdx.y;         // 0..23
    const int b = bh / Hn, h = bh % Hn;
    const int r = threadIdx.x;         // 0..127
    const int i0 = bx * 128;
    const int i = i0 + r;

    __shared__ float Ks[32][64];
    __shared__ float Vs[32][64];
    __shared__ float Fs[128][33];      // pad 33 -> conflict-free per-row reads

    const float* qrow = g_qkv + ((long)(b * Tn + i)) * QKVn + h * HDn;
    float4 q4[16];
    #pragma unroll
    for (int u = 0; u < 16; u++) q4[u] = *(const float4*)(qrow + u * 4);

    float4 o4[16];
    #pragma unroll
    for (int u = 0; u < 16; u++) o4[u] = make_float4(0.f, 0.f, 0.f, 0.f);
    float m = -INFINITY, l = 0.f;

    const float* kbase = g_qkv + (long)b * Tn * QKVn + Cn + h * HDn;        // K slice
    const float* vbase = kbase + Cn;                                         // V slice
    const float* fbase = g_ff + (long)b * Tn * Tn;

    const int ntiles = (i0 + 128) / 32;
    for (int t = 0; t < ntiles; t++) {
        const int j0 = t * 32;
        __syncthreads();
        {   // K/V tile: thread -> (jj = r/4, d0 = (r%4)*16), 4 float4 each
            const int jj = r >> 2, d0 = (r & 3) * 16;
            const float* kp = kbase + (long)(j0 + jj) * QKVn + d0;
            const float* vp = vbase + (long)(j0 + jj) * QKVn + d0;
            #pragma unroll
            for (int u = 0; u < 4; u++) {
                *(float4*)&Ks[jj][d0 + u * 4] = *(const float4*)(kp + u * 4);
                *(float4*)&Vs[jj][d0 + u * 4] = *(const float4*)(vp + u * 4);
            }
        }
        #pragma unroll
        for (int it = 0; it < 8; it++) {   // FF tile, coalesced rows
            const int lin = it * 512 + r * 4;
            const int rr = lin >> 5, jj = lin & 31;
            float4 f = *(const float4*)(fbase + (long)(i0 + rr) * Tn + j0 + jj);
            Fs[rr][jj + 0] = f.x; Fs[rr][jj + 1] = f.y;
            Fs[rr][jj + 2] = f.z; Fs[rr][jj + 3] = f.w;
        }
        __syncthreads();

        const int jmax = min(32, i - j0 + 1);
        for (int jj = 0; jj < jmax; jj++) {
            float dot = 0.f;
            #pragma unroll
            for (int u = 0; u < 16; u++) {
                float4 kv = *(const float4*)&Ks[jj][u * 4];
                dot += q4[u].x * kv.x + q4[u].y * kv.y
                     + q4[u].z * kv.z + q4[u].w * kv.w;
            }
            const float logit = dot * SCALE - Fs[r][jj];
            if (logit > m) {
                const float f = __expf(m - logit);
                l *= f;
                #pragma unroll
                for (int u = 0; u < 16; u++) {
                    o4[u].x *= f; o4[u].y *= f; o4[u].z *= f; o4[u].w *= f;
                }
                m = logit;
            }
            const float p = __expf(logit - m);
            l += p;
            #pragma unroll
            for (int u = 0; u < 16; u++) {
                float4 vv = *(const float4*)&Vs[jj][u * 4];
                o4[u].x += p * vv.x; o4[u].y += p * vv.y;
                o4[u].z += p * vv.z; o4[u].w += p * vv.w;
            }
        }
    }

    const float inv = 1.f / l;
    float* yp = g_y + ((long)(b * Tn + i)) * Cn + h * HDn;
    #pragma unroll
    for (int u = 0; u < 16; u++) {
        float4 o = o4[u];
        o.x *= inv; o.y *= inv; o.z *= inv; o.w *= inv;
        *(float4*)(yp + u * 4) = o;
    }
}

// ============================================================================
extern "C" void kernel_launch(void* const* d_in, const int* in_sizes, int n_in,
                              void* d_out, int out_size)
{
    const float* x      = (const float*)d_in[0];  // [B,T,C]
    const float* w_attn = (const float*)d_in[1];  // [2304, 768]
    const float* b_attn = (const float*)d_in[2];  // [2304]
    const float* w_proj = (const float*)d_in[3];  // [768, 768]
    const float* b_proj = (const float*)d_in[4];  // [768]
    const float* sel_w  = (const float*)d_in[5];  // [12]
    float* out = (float*)d_out;                   // [B,T,C] fp32

    float *qkv, *qs, *ff, *y;
    cudaGetSymbolAddress((void**)&qkv, g_qkv);
    cudaGetSymbolAddress((void**)&qs,  g_qs);
    cudaGetSymbolAddress((void**)&ff,  g_ff);
    cudaGetSymbolAddress((void**)&y,   g_y);

    // 1) qkv = x @ w_attn^T + b_attn  (+ scatter sel_w-scaled q)
    sgemm_nt<0><<<dim3(QKVn / 128, (Bn * Tn) / 128, 1), 256>>>(
        x, Cn, 0, w_attn, Cn, 0, qkv, QKVn, 0, Cn, b_attn, sel_w);

    // 2) S[b] = relu(scale * qs[b] @ kcat[b]^T) masked (causal, no diag, no col0)
    sgemm_nt<1><<<dim3(Tn / 128, Tn / 128, Bn), 256>>>(
        qs, Cn, (long)Tn * Cn,
        qkv + Cn, QKVn, (long)Tn * QKVn,
        ff, Tn, (long)Tn * Tn,
        Cn, nullptr, nullptr);

    // 3) FF_shifted = exclusive cumsum of S over rows (in place)
    cumsum_kernel<<<(Bn * Tn) / 256, 256>>>();

    // 4) attention with forgetting term
    attn_kernel<<<dim3(Tn / 128, Bn * Hn), 128>>>();

    // 5) out = y @ w_proj^T + b_proj
    sgemm_nt<2><<<dim3(Cn / 128, (Bn * Tn) / 128, 1), 256>>>(
        y, Cn, 0, w_proj, Cn, 0, out, Cn, 0, Cn, b_proj, nullptr);
}

// round 2
// speedup vs baseline: 1.0154x; 1.0154x over previous
#include <cuda_runtime.h>
#include <math.h>

#define Bn   2
#define Tn   2048
#define Cn   768
#define Hn   12
#define HDn  64
#define QKVn 2304
#define SCALE 0.125f   // 1/sqrt(64)
#define NSEG 16        // cumsum segments (128 rows each)

// -------- device scratch (no allocations allowed) --------
__device__ float g_qkv [Bn * Tn * QKVn];   // qkv = x@w_attn^T + b   [B*T, 2304]
__device__ float g_qs  [Bn * Tn * Cn];     // sel_w-scaled concat-q  [B*T, 768]
__device__ float g_ff  [Bn * Tn * Tn];     // S, then exclusive cumsum (FF_shifted)
__device__ float g_y   [Bn * Tn * Cn];     // attention output       [B*T, 768]
__device__ float g_part[Bn * NSEG * Tn];   // cumsum segment partials

// -------- packed f32x2 helpers (B300 double-rate fp32) --------
__device__ __forceinline__ unsigned long long pk2(float x, float y) {
    unsigned long long r; asm("mov.b64 %0, {%1, %2};" : "=l"(r) : "f"(x), "f"(y)); return r;
}
__device__ __forceinline__ float2 up2(unsigned long long v) {
    float2 r; asm("mov.b64 {%0, %1}, %2;" : "=f"(r.x), "=f"(r.y) : "l"(v)); return r;
}
__device__ __forceinline__ void fma2(unsigned long long& d,
                                     unsigned long long a, unsigned long long b) {
    asm("fma.rn.f32x2 %0, %1, %2, %0;" : "+l"(d) : "l"(a), "l"(b));
}
__device__ __forceinline__ unsigned long long mul2(unsigned long long a, unsigned long long b) {
    unsigned long long r; asm("mul.rn.f32x2 %0, %1, %2;" : "=l"(r) : "l"(a), "l"(b)); return r;
}

// ============================================================================
// Generic NT SGEMM via f32x2: C[m,n] = sum_k A[m,k]*B[n,k]
// 128x128 tile, BK=8, 256 threads, 8x8 microtile packed as 8x4 f32x2.
// MODE 0: qkv epilogue (bias + scatter scaled q), MODE 1: S epilogue, MODE 2: proj.
// ============================================================================
template <int MODE>
__global__ void __launch_bounds__(256)
sgemm_nt(const float* __restrict__ A, int lda, long sA,
         const float* __restrict__ Bm, int ldb, long sB,
         float* __restrict__ C, int ldc, long sC,
         int K,
         const float* __restrict__ bias,
         const float* __restrict__ selw)
{
    const int bx = blockIdx.x, by = blockIdx.y, bz = blockIdx.z;
    const int i0 = by * 128, j0 = bx * 128;
    if (MODE == 1 && j0 >= i0 + 128) return;   // strictly-upper tile: skip

    A  += (long)bz * sA;
    Bm += (long)bz * sB;
    C  += (long)bz * sC;

    __shared__ __align__(16) float As[8][132];
    __shared__ __align__(16) float Bs[8][132];

    const int tid = threadIdx.x;
    const int tx = tid & 15, ty = tid >> 4;
    const int lr = tid >> 1;
    const int lk = (tid & 1) * 4;

    unsigned long long acc2[8][4];
    #pragma unroll
    for (int a = 0; a < 8; a++)
        #pragma unroll
        for (int b = 0; b < 4; b++) acc2[a][b] = 0ull;

    for (int k0 = 0; k0 < K; k0 += 8) {
        float4 av = *(const float4*)(A  + (long)(i0 + lr) * lda + k0 + lk);
        float4 bv = *(const float4*)(Bm + (long)(j0 + lr) * ldb + k0 + lk);
        As[lk + 0][lr] = av.x; As[lk + 1][lr] = av.y;
        As[lk + 2][lr] = av.z; As[lk + 3][lr] = av.w;
        Bs[lk + 0][lr] = bv.x; Bs[lk + 1][lr] = bv.y;
        Bs[lk + 2][lr] = bv.z; Bs[lk + 3][lr] = bv.w;
        __syncthreads();

        #pragma unroll
        for (int kk = 0; kk < 8; kk++) {
            unsigned long long bb[4];
            #pragma unroll
            for (int j2 = 0; j2 < 4; j2++)
                bb[j2] = *(const unsigned long long*)&Bs[kk][tx * 8 + j2 * 2];
            #pragma unroll
            for (int ii = 0; ii < 8; ii++) {
                float avv = As[kk][ty * 8 + ii];
                unsigned long long aa = pk2(avv, avv);
                #pragma unroll
                for (int j2 = 0; j2 < 4; j2++)
                    fma2(acc2[ii][j2], aa, bb[j2]);
            }
        }
        __syncthreads();
    }

    #pragma unroll
    for (int ii = 0; ii < 8; ii++) {
        const int m = i0 + ty * 8 + ii;
        #pragma unroll
        for (int j2 = 0; j2 < 4; j2++) {
            const int n = j0 + tx * 8 + j2 * 2;
            float2 v = up2(acc2[ii][j2]);
            if (MODE == 0) {
                float r0 = v.x + bias[n], r1 = v.y + bias[n + 1];
                C[(long)m * ldc + n]     = r0;
                C[(long)m * ldc + n + 1] = r1;
                if (n < Cn) {
                    g_qs[(long)m * Cn + n]     = r0 * selw[n >> 6];
                    g_qs[(long)m * Cn + n + 1] = r1 * selw[(n + 1) >> 6];
                }
            } else if (MODE == 1) {
                const int i = m;
                float r0 = v.x * SCALE, r1 = v.y * SCALE;
                r0 = (n     >= 1 && n     < i) ? fmaxf(r0, 0.f) : 0.f;
                r1 = (n + 1 >= 1 && n + 1 < i) ? fmaxf(r1, 0.f) : 0.f;
                C[(long)i * ldc + n]     = r0;
                C[(long)i * ldc + n + 1] = r1;
            } else {
                C[(long)m * ldc + n]     = v.x + bias[n];
                C[(long)m * ldc + n + 1] = v.y + bias[n + 1];
            }
        }
    }
}

// ============================================================================
// Parallel exclusive cumsum of S over rows i: two phases, 65536 threads each.
// ============================================================================
__global__ void cumsum_p1()
{
    const int g = blockIdx.x * 256 + threadIdx.x;   // b*NSEG*Tn + seg*Tn + j
    const int j = g & (Tn - 1);
    const int seg = (g >> 11) & (NSEG - 1);
    const int b = g >> 15;
    const float* col = g_ff + (long)b * Tn * Tn + j;
    const int ibeg = seg * 128;
    float s = 0.f;
    #pragma unroll 4
    for (int k = 0; k < 128; k++) {
        const int i = ibeg + k;
        const float v = col[(long)i * Tn];
        if (i > j) s += v;
    }
    g_part[g] = s;
}

__global__ void cumsum_p2()
{
    const int g = blockIdx.x * 256 + threadIdx.x;
    const int j = g & (Tn - 1);
    const int seg = (g >> 11) & (NSEG - 1);
    const int b = g >> 15;
    const float* pp = g_part + (b << 15) + j;
    float acc = 0.f;
    for (int s2 = 0; s2 < seg; s2++) acc += pp[s2 << 11];
    float* col = g_ff + (long)b * Tn * Tn + j;
    const int ibeg = seg * 128;
    #pragma unroll 4
    for (int k = 0; k < 128; k++) {
        const int i = ibeg + k;
        const float v = col[(long)i * Tn];
        col[(long)i * Tn] = acc;       // exclusive prefix (FF_shifted)
        if (i > j) acc += v;
    }
}

// ============================================================================
// Attention: per (b,h), 64 query rows per block of 128 threads.
// Thread = 2 rows x 16 dims (4 threads/row, shfl-combined dots).
// Tile-phased online softmax: batch dots -> tile max -> batch exp -> batched PV.
// ============================================================================
__global__ void __launch_bounds__(128) attn_kernel()
{
    const int bx = blockIdx.x;          // row tile (64 rows): 0..31
    const int bh = blockIdx.y;          // 0..23
    const int b = bh / Hn, h = bh % Hn;
    const int tid = threadIdx.x;
    const int qd = tid & 3;             // dim quarter: [qd*16, qd*16+16)
    const int rg = tid >> 2;            // row group 0..31
    const int i0 = bx * 64;
    const int r0 = rg * 2, r1 = r0 + 1;
    const int ia = i0 + r0, ib = i0 + r1;

    __shared__ __align__(16) float Ks[32][64];
    __shared__ __align__(16) float Vs[32][64];
    __shared__ float Fs[64][33];

    // q for both rows, packed
    unsigned long long q0[8], q1[8], o0[8], o1[8];
    {
        const float* qa = g_qkv + ((long)(b * Tn + ia)) * QKVn + h * HDn + qd * 16;
        const float* qb = qa + QKVn;
        #pragma unroll
        for (int u = 0; u < 8; u++) {
            q0[u] = *(const unsigned long long*)(qa + u * 2);
            q1[u] = *(const unsigned long long*)(qb + u * 2);
            o0[u] = 0ull; o1[u] = 0ull;
        }
    }
    float m0 = -INFINITY, l0 = 0.f, m1 = -INFINITY, l1 = 0.f;

    const float* kbase = g_qkv + (long)b * Tn * QKVn + Cn + h * HDn;
    const float* vbase = kbase + Cn;
    const float* fbase = g_ff + (long)b * Tn * Tn;

    const int ntiles = i0 / 32 + 2;
    for (int t = 0; t < ntiles; t++) {
        const int j0 = t * 32;
        __syncthreads();
        {   // K/V tile: thread -> (row = tid>>2, 16-float seg = (tid&3)*16)
            const int jj = tid >> 2, d0 = (tid & 3) * 16;
            const float* kp = kbase + (long)(j0 + jj) * QKVn + d0;
            const float* vp = vbase + (long)(j0 + jj) * QKVn + d0;
            #pragma unroll
            for (int u = 0; u < 4; u++) {
                *(float4*)&Ks[jj][d0 + u * 4] = *(const float4*)(kp + u * 4);
                *(float4*)&Vs[jj][d0 + u * 4] = *(const float4*)(vp + u * 4);
            }
            // F tile: thread -> (row = tid>>1, 16-float seg = (tid&1)*16)
            const int fr = tid >> 1, fc = (tid & 1) * 16;
            const float* fp = fbase + (long)(i0 + fr) * Tn + j0 + fc;
            #pragma unroll
            for (int u = 0; u < 4; u++) {
                float4 f = *(const float4*)(fp + u * 4);
                Fs[fr][fc + u * 4 + 0] = f.x; Fs[fr][fc + u * 4 + 1] = f.y;
                Fs[fr][fc + u * 4 + 2] = f.z; Fs[fr][fc + u * 4 + 3] = f.w;
            }
        }
        __syncthreads();

        // Phase A: 32 dots per row (independent chains), shfl-combined
        float s0[32], s1[32];
        #pragma unroll
        for (int jj = 0; jj < 32; jj++) {
            unsigned long long a0 = 0ull, a1 = 0ull;
            const unsigned long long* kp = (const unsigned long long*)&Ks[jj][qd * 16];
            #pragma unroll
            for (int u = 0; u < 8; u++) {
                const unsigned long long kv = kp[u];
                fma2(a0, q0[u], kv);
                fma2(a1, q1[u], kv);
            }
            float2 f0 = up2(a0), f1 = up2(a1);
            float d0 = f0.x + f0.y, d1 = f1.x + f1.y;
            d0 += __shfl_xor_sync(0xffffffffu, d0, 1);
            d0 += __shfl_xor_sync(0xffffffffu, d0, 2);
            d1 += __shfl_xor_sync(0xffffffffu, d1, 1);
            d1 += __shfl_xor_sync(0xffffffffu, d1, 2);
            const int j = j0 + jj;
            const float e0 = d0 * SCALE - Fs[r0][jj];
            const float e1 = d1 * SCALE - Fs[r1][jj];
            s0[jj] = (j <= ia) ? e0 : -INFINITY;
            s1[jj] = (j <= ib) ? e1 : -INFINITY;
        }

        // Phase B/C: tile max, rescale, batch exp
        float tm0 = -INFINITY, tm1 = -INFINITY;
        #pragma unroll
        for (int jj = 0; jj < 32; jj++) {
            tm0 = fmaxf(tm0, s0[jj]);
            tm1 = fmaxf(tm1, s1[jj]);
        }
        const float mn0 = fmaxf(m0, tm0), mn1 = fmaxf(m1, tm1);
        const float sc0 = __expf(m0 - mn0), sc1 = __expf(m1 - mn1);
        float sum0 = 0.f, sum1 = 0.f;
        #pragma unroll
        for (int jj = 0; jj < 32; jj++) {
            const float p0 = __expf(s0[jj] - mn0);
            const float p1 = __expf(s1[jj] - mn1);
            s0[jj] = p0; s1[jj] = p1;
            sum0 += p0; sum1 += p1;
        }
        l0 = l0 * sc0 + sum0; m0 = mn0;
        l1 = l1 * sc1 + sum1; m1 = mn1;
        {
            const unsigned long long sc02 = pk2(sc0, sc0);
            const unsigned long long sc12 = pk2(sc1, sc1);
            #pragma unroll
            for (int u = 0; u < 8; u++) {
                o0[u] = mul2(o0[u], sc02);
                o1[u] = mul2(o1[u], sc12);
            }
        }

        // Phase D: batched PV
        #pragma unroll
        for (int jj = 0; jj < 32; jj++) {
            const unsigned long long p02 = pk2(s0[jj], s0[jj]);
            const unsigned long long p12 = pk2(s1[jj], s1[jj]);
            const unsigned long long* vp = (const unsigned long long*)&Vs[jj][qd * 16];
            #pragma unroll
            for (int u = 0; u < 8; u++) {
                const unsigned long long vv = vp[u];
                fma2(o0[u], p02, vv);
                fma2(o1[u], p12, vv);
            }
        }
    }

    const float inv0 = 1.f / l0, inv1 = 1.f / l1;
    float* ya = g_y + (long)(b * Tn + ia) * Cn + h * HDn + qd * 16;
    float* yb = ya + Cn;
    #pragma unroll
    for (int u = 0; u < 4; u++) {
        float2 e0 = up2(o0[2 * u]), e1 = up2(o0[2 * u + 1]);
        *(float4*)(ya + u * 4) = make_float4(e0.x * inv0, e0.y * inv0, e1.x * inv0, e1.y * inv0);
        float2 g0 = up2(o1[2 * u]), g1 = up2(o1[2 * u + 1]);
        *(float4*)(yb + u * 4) = make_float4(g0.x * inv1, g0.y * inv1, g1.x * inv1, g1.y * inv1);
    }
}

// ============================================================================
extern "C" void kernel_launch(void* const* d_in, const int* in_sizes, int n_in,
                              void* d_out, int out_size)
{
    const float* x      = (const float*)d_in[0];  // [B,T,C]
    const float* w_attn = (const float*)d_in[1];  // [2304, 768]
    const float* b_attn = (const float*)d_in[2];  // [2304]
    const float* w_proj = (const float*)d_in[3];  // [768, 768]
    const float* b_proj = (const float*)d_in[4];  // [768]
    const float* sel_w  = (const float*)d_in[5];  // [12]
    float* out = (float*)d_out;                   // [B,T,C] fp32

    float *qkv, *qs, *ff, *y;
    cudaGetSymbolAddress((void**)&qkv, g_qkv);
    cudaGetSymbolAddress((void**)&qs,  g_qs);
    cudaGetSymbolAddress((void**)&ff,  g_ff);
    cudaGetSymbolAddress((void**)&y,   g_y);

    // 1) qkv = x @ w_attn^T + b_attn  (+ scatter sel_w-scaled q)
    sgemm_nt<0><<<dim3(QKVn / 128, (Bn * Tn) / 128, 1), 256>>>(
        x, Cn, 0, w_attn, Cn, 0, qkv, QKVn, 0, Cn, b_attn, sel_w);

    // 2) S[b] = relu(scale * qs[b] @ kcat[b]^T) masked (causal, no diag, no col0)
    sgemm_nt<1><<<dim3(Tn / 128, Tn / 128, Bn), 256>>>(
        qs, Cn, (long)Tn * Cn,
        qkv + Cn, QKVn, (long)Tn * QKVn,
        ff, Tn, (long)Tn * Tn,
        Cn, nullptr, nullptr);

    // 3) FF_shifted = exclusive cumsum of S over rows (parallel, two phases)
    cumsum_p1<<<(Bn * NSEG * Tn) / 256, 256>>>();
    cumsum_p2<<<(Bn * NSEG * Tn) / 256, 256>>>();

    // 4) attention with forgetting term
    attn_kernel<<<dim3(Tn / 64, Bn * Hn), 128>>>();

    // 5) out = y @ w_proj^T + b_proj
    sgemm_nt<2><<<dim3(Cn / 128, (Bn * Tn) / 128, 1), 256>>>(
        y, Cn, 0, w_proj, Cn, 0, out, Cn, 0, Cn, b_proj, nullptr);
}

// round 5
// speedup vs baseline: 1.2501x; 1.2311x over previous
#include <cuda_runtime.h>
#include <cuda_bf16.h>
#include <math.h>
#include <stdint.h>

#define Bn   2
#define Tn   2048
#define Cn   768
#define Hn   12
#define HDn  64
#define QKVn 2304
#define SCALE 0.125f   // 1/sqrt(64)
#define NSEG 32        // cumsum segments (64 rows each)

// -------- device scratch (no allocations allowed) --------
__device__ float g_qkv [Bn * Tn * QKVn];     // qkv fp32 (attn reads q/k/v)
__device__ float g_ff  [Bn * Tn * Tn];       // S, then exclusive cumsum
__device__ float g_part[Bn * NSEG * Tn];     // cumsum segment partials
__device__ __nv_bfloat16 g_xh [Bn*Tn*Cn], g_xl [Bn*Tn*Cn];
__device__ __nv_bfloat16 g_wah[QKVn*Cn],  g_wal[QKVn*Cn];
__device__ __nv_bfloat16 g_wph[Cn*Cn],    g_wpl[Cn*Cn];
__device__ __nv_bfloat16 g_qsh[Bn*Tn*Cn], g_qsl[Bn*Tn*Cn];  // sel_w-scaled q
__device__ __nv_bfloat16 g_kh [Bn*Tn*Cn], g_kl [Bn*Tn*Cn];
__device__ __nv_bfloat16 g_yh [Bn*Tn*Cn], g_yl [Bn*Tn*Cn];

// ======================= PTX helpers (compute_103-safe) ====================
__device__ __forceinline__ uint32_t smem_u32(const void* p) {
    uint32_t a;
    asm("{ .reg .u64 t; cvta.to.shared.u64 t, %1; cvt.u32.u64 %0, t; }"
        : "=r"(a) : "l"(p));
    return a;
}
__device__ __forceinline__ void ldsm4(uint32_t* r, uint32_t addr) {
    asm volatile("ldmatrix.sync.aligned.m8n8.x4.shared.b16 {%0,%1,%2,%3}, [%4];"
                 : "=r"(r[0]), "=r"(r[1]), "=r"(r[2]), "=r"(r[3]) : "r"(addr));
}
__device__ __forceinline__ void mma16816(float* c, const uint32_t* a, const uint32_t* b) {
    asm volatile(
        "mma.sync.aligned.m16n8k16.row.col.f32.bf16.bf16.f32 "
        "{%0,%1,%2,%3}, {%4,%5,%6,%7}, {%8,%9}, {%0,%1,%2,%3};"
        : "+f"(c[0]), "+f"(c[1]), "+f"(c[2]), "+f"(c[3])
        : "r"(a[0]), "r"(a[1]), "r"(a[2]), "r"(a[3]), "r"(b[0]), "r"(b[1]));
}
__device__ __forceinline__ void cpasync16(uint32_t dst, const void* src) {
    asm volatile("cp.async.cg.shared.global [%0], [%1], 16;" :: "r"(dst), "l"(src));
}

// -------- packed f32x2 helpers (used by attention) --------
__device__ __forceinline__ unsigned long long pk2(float x, float y) {
    unsigned long long r; asm("mov.b64 %0, {%1, %2};" : "=l"(r) : "f"(x), "f"(y)); return r;
}
__device__ __forceinline__ float2 up2(unsigned long long v) {
    float2 r; asm("mov.b64 {%0, %1}, %2;" : "=f"(r.x), "=f"(r.y) : "l"(v)); return r;
}
__device__ __forceinline__ void fma2(unsigned long long& d,
                                     unsigned long long a, unsigned long long b) {
    asm("fma.rn.f32x2 %0, %1, %2, %0;" : "+l"(d) : "l"(a), "l"(b));
}
__device__ __forceinline__ unsigned long long mul2(unsigned long long a, unsigned long long b) {
    unsigned long long r; asm("mul.rn.f32x2 %0, %1, %2;" : "=l"(r) : "l"(a), "l"(b)); return r;
}

// ============================================================================
// bf16 split helper: src fp32 -> (hi, lo) bf16
// ============================================================================
__global__ void split_bf16(const float* __restrict__ src,
                           __nv_bfloat16* __restrict__ h,
                           __nv_bfloat16* __restrict__ l, int n)
{
    int i = blockIdx.x * 256 + threadIdx.x;
    if (i < n) {
        float v = src[i];
        __nv_bfloat16 hh = __float2bfloat16(v);
        h[i] = hh;
        l[i] = __float2bfloat16(v - __bfloat162float(hh));
    }
}

// ============================================================================
// bf16x3 tensor-core GEMM via mma.sync (HMMA): C[m,n]=sum_k A[m,k]*B[n,k]
// A=Ah+Al, B=Bh+Bl, products AhBh+AhBl+AlBh, fp32 accum.
// 128x128 block, BK=16, 8 warps (64x32 warp tile), cp.async double buffer.
// Smem rows padded to 48B -> conflict-free ldmatrix. K must be 768.
// MODE 0 qkv / 1 selection-S / 2 proj.
// ============================================================================
#define TILEB 6144          // 128 rows * 48 bytes
#define STAGEB (4 * TILEB)  // Ah, Al, Bh, Bl

template <int MODE>
__global__ void __launch_bounds__(256)
gemm_mma(const __nv_bfloat16* __restrict__ Ah, const __nv_bfloat16* __restrict__ Al,
         const __nv_bfloat16* __restrict__ Bh, const __nv_bfloat16* __restrict__ Bl,
         int lda, int ldb, long sA, long sB,
         const float* __restrict__ bias, const float* __restrict__ selw,
         float* __restrict__ Cout)
{
    const int i0 = blockIdx.y * 128, j0 = blockIdx.x * 128, bz = blockIdx.z;
    if (MODE == 1 && j0 > i0) return;        // strictly-upper tiles: zero, never read
    Ah += (long)bz * sA; Al += (long)bz * sA;
    Bh += (long)bz * sB; Bl += (long)bz * sB;

    __shared__ __align__(128) char sm[2 * STAGEB];   // 48 KB
    const uint32_t sb = smem_u32(sm);

    const int tid = threadIdx.x;
    const int lane = tid & 31, wid = tid >> 5;
    const int wm = (wid & 1) * 64, wn = (wid >> 1) * 32;

    // ---- cp.async mapping: thread -> (row = tid/2, 16B half = tid&1), 4 tiles
    const int lrow = tid >> 1, lhalf = tid & 1;
    const __nv_bfloat16* srcs[4] = {
        Ah + (long)(i0 + lrow) * lda + lhalf * 8,
        Al + (long)(i0 + lrow) * lda + lhalf * 8,
        Bh + (long)(j0 + lrow) * ldb + lhalf * 8,
        Bl + (long)(j0 + lrow) * ldb + lhalf * 8 };
    const uint32_t dstb = sb + lrow * 48 + lhalf * 16;

    // ---- ldmatrix lane addresses (within stage 0)
    uint32_t a_addr[4], b_addr[2];
    {
        const int r = wm + (lane & 15);
        const int c = (lane >> 4) * 16;
        #pragma unroll
        for (int mi = 0; mi < 4; mi++)
            a_addr[mi] = sb + (r + mi * 16) * 48 + c;
        const int n = wn + (lane & 7) + (lane >> 4) * 8;
        const int kc = ((lane >> 3) & 1) * 16;
        #pragma unroll
        for (int nc = 0; nc < 2; nc++)
            b_addr[nc] = sb + 2 * TILEB + (n + nc * 16) * 48 + kc;
    }

    float acc[4][4][4];
    #pragma unroll
    for (int mi = 0; mi < 4; mi++)
        #pragma unroll
        for (int ni = 0; ni < 4; ni++)
            #pragma unroll
            for (int e = 0; e < 4; e++) acc[mi][ni][e] = 0.f;

    const int NT = Cn / 16;    // 48
    auto load_stage = [&](int t) {
        const uint32_t off = (t & 1) * STAGEB;
        const int k0 = t * 16;
        #pragma unroll
        for (int m4 = 0; m4 < 4; m4++)
            cpasync16(dstb + off + m4 * TILEB, (const void*)(srcs[m4] + k0));
        asm volatile("cp.async.commit_group;");
    };

    load_stage(0);
    for (int t = 0; t < NT; t++) {
        if (t + 1 < NT) {
            load_stage(t + 1);
            asm volatile("cp.async.wait_group 1;");
        } else {
            asm volatile("cp.async.wait_group 0;");
        }
        __syncthreads();

        const uint32_t off = (t & 1) * STAGEB;
        uint32_t fah[4][4], fal[4][4], fbh[2][4], fbl[2][4];
        #pragma unroll
        for (int mi = 0; mi < 4; mi++) {
            ldsm4(fah[mi], a_addr[mi] + off);
            ldsm4(fal[mi], a_addr[mi] + off + TILEB);
        }
        #pragma unroll
        for (int nc = 0; nc < 2; nc++) {
            ldsm4(fbh[nc], b_addr[nc] + off);
            ldsm4(fbl[nc], b_addr[nc] + off + TILEB);
        }
        #pragma unroll
        for (int mi = 0; mi < 4; mi++)
            #pragma unroll
            for (int ni = 0; ni < 4; ni++) {
                const int nc = ni >> 1, sel = (ni & 1) * 2;
                mma16816(acc[mi][ni], fah[mi], &fbh[nc][sel]);
                mma16816(acc[mi][ni], fah[mi], &fbl[nc][sel]);
                mma16816(acc[mi][ni], fal[mi], &fbh[nc][sel]);
            }
        __syncthreads();
    }

    // ---- epilogue: lane holds (g, 2t),(g,2t+1),(g+8,2t),(g+8,2t+1) per frag
    const int g = lane >> 2, t4 = lane & 3;
    #pragma unroll
    for (int mi = 0; mi < 4; mi++) {
        #pragma unroll
        for (int ni = 0; ni < 4; ni++) {
            const int col = j0 + wn + ni * 8 + t4 * 2;
            #pragma unroll
            for (int e = 0; e < 4; e++) {
                const int m = i0 + wm + mi * 16 + g + (e >> 1) * 8;
                const int n = col + (e & 1);
                const float raw = acc[mi][ni][e];
                if (MODE == 0) {
                    const float v = raw + bias[n];
                    g_qkv[(long)m * QKVn + n] = v;
                    if (n < Cn) {
                        const float qv = v * selw[n >> 6];
                        __nv_bfloat16 h = __float2bfloat16(qv);
                        g_qsh[(long)m * Cn + n] = h;
                        g_qsl[(long)m * Cn + n] =
                            __float2bfloat16(qv - __bfloat162float(h));
                    } else if (n < 2 * Cn) {
                        __nv_bfloat16 h = __float2bfloat16(v);
                        g_kh[(long)m * Cn + n - Cn] = h;
                        g_kl[(long)m * Cn + n - Cn] =
                            __float2bfloat16(v - __bfloat162float(h));
                    }
                } else if (MODE == 1) {
                    float v = raw * SCALE;
                    v = (n >= 1 && n < m) ? fmaxf(v, 0.f) : 0.f;
                    g_ff[(long)bz * Tn * Tn + (long)m * Tn + n] = v;
                } else {
                    Cout[(long)m * Cn + n] = raw + bias[n];
                }
            }
        }
    }
}

// ============================================================================
// Parallel exclusive cumsum of S over rows i (NSEG=32 segments of 64 rows)
// ============================================================================
__global__ void cumsum_p1()
{
    const int g = blockIdx.x * 256 + threadIdx.x;
    const int j = g & (Tn - 1);
    const int seg = (g >> 11) & (NSEG - 1);
    const int b = g >> 16;
    const float* col = g_ff + (long)b * Tn * Tn + j;
    const int ibeg = seg * (Tn / NSEG);
    float s = 0.f;
    #pragma unroll 8
    for (int k = 0; k < Tn / NSEG; k++) {
        const int i = ibeg + k;
        const float v = col[(long)i * Tn];
        if (i > j) s += v;
    }
    g_part[g] = s;
}

__global__ void cumsum_p2()
{
    const int g = blockIdx.x * 256 + threadIdx.x;
    const int j = g & (Tn - 1);
    const int seg = (g >> 11) & (NSEG - 1);
    const int b = g >> 16;
    const float* pp = g_part + (b << 16) + j;
    float acc = 0.f;
    for (int s2 = 0; s2 < seg; s2++) acc += pp[s2 << 11];
    float* col = g_ff + (long)b * Tn * Tn + j;
    const int ibeg = seg * (Tn / NSEG);
    #pragma unroll 8
    for (int k = 0; k < Tn / NSEG; k++) {
        const int i = ibeg + k;
        const float v = col[(long)i * Tn];
        col[(long)i * Tn] = acc;          // exclusive prefix (FF_shifted)
        if (i > j) acc += v;
    }
}

// ============================================================================
// Attention: per (b,h), 64 query rows per block of 128 threads.
// Thread = 2 rows x 16 dims; tile-phased online softmax; writes y as bf16 h/l.
// ============================================================================
__global__ void __launch_bounds__(128) attn_kernel()
{
    const int bx = blockIdx.x;
    const int bh = blockIdx.y;
    const int b = bh / Hn, h = bh % Hn;
    const int tid = threadIdx.x;
    const int qd = tid & 3;
    const int rg = tid >> 2;
    const int i0 = bx * 64;
    const int r0 = rg * 2, r1 = r0 + 1;
    const int ia = i0 + r0, ib = i0 + r1;

    __shared__ __align__(16) float Ks[32][64];
    __shared__ __align__(16) float Vs[32][64];
    __shared__ float Fs[64][33];

    unsigned long long q0[8], q1[8], o0[8], o1[8];
    {
        const float* qa = g_qkv + ((long)(b * Tn + ia)) * QKVn + h * HDn + qd * 16;
        const float* qb = qa + QKVn;
        #pragma unroll
        for (int u = 0; u < 8; u++) {
            q0[u] = *(const unsigned long long*)(qa + u * 2);
            q1[u] = *(const unsigned long long*)(qb + u * 2);
            o0[u] = 0ull; o1[u] = 0ull;
        }
    }
    float m0 = -INFINITY, l0 = 0.f, m1 = -INFINITY, l1 = 0.f;

    const float* kbase = g_qkv + (long)b * Tn * QKVn + Cn + h * HDn;
    const float* vbase = kbase + Cn;
    const float* fbase = g_ff + (long)b * Tn * Tn;

    const int ntiles = i0 / 32 + 2;
    for (int t = 0; t < ntiles; t++) {
        const int j0 = t * 32;
        __syncthreads();
        {
            const int jj = tid >> 2, d0 = (tid & 3) * 16;
            const float* kp = kbase + (long)(j0 + jj) * QKVn + d0;
            const float* vp = vbase + (long)(j0 + jj) * QKVn + d0;
            #pragma unroll
            for (int u = 0; u < 4; u++) {
                *(float4*)&Ks[jj][d0 + u * 4] = *(const float4*)(kp + u * 4);
                *(float4*)&Vs[jj][d0 + u * 4] = *(const float4*)(vp + u * 4);
            }
            const int fr = tid >> 1, fc = (tid & 1) * 16;
            const float* fp = fbase + (long)(i0 + fr) * Tn + j0 + fc;
            #pragma unroll
            for (int u = 0; u < 4; u++) {
                float4 f = *(const float4*)(fp + u * 4);
                Fs[fr][fc + u * 4 + 0] = f.x; Fs[fr][fc + u * 4 + 1] = f.y;
                Fs[fr][fc + u * 4 + 2] = f.z; Fs[fr][fc + u * 4 + 3] = f.w;
            }
        }
        __syncthreads();

        float s0[32], s1[32];
        #pragma unroll
        for (int jj = 0; jj < 32; jj++) {
            unsigned long long a0 = 0ull, a1 = 0ull;
            const unsigned long long* kp = (const unsigned long long*)&Ks[jj][qd * 16];
            #pragma unroll
            for (int u = 0; u < 8; u++) {
                const unsigned long long kv = kp[u];
                fma2(a0, q0[u], kv);
                fma2(a1, q1[u], kv);
            }
            float2 f0 = up2(a0), f1 = up2(a1);
            float d0 = f0.x + f0.y, d1 = f1.x + f1.y;
            d0 += __shfl_xor_sync(0xffffffffu, d0, 1);
            d0 += __shfl_xor_sync(0xffffffffu, d0, 2);
            d1 += __shfl_xor_sync(0xffffffffu, d1, 1);
            d1 += __shfl_xor_sync(0xffffffffu, d1, 2);
            const int j = j0 + jj;
            const float e0 = d0 * SCALE - Fs[r0][jj];
            const float e1 = d1 * SCALE - Fs[r1][jj];
            s0[jj] = (j <= ia) ? e0 : -INFINITY;
            s1[jj] = (j <= ib) ? e1 : -INFINITY;
        }

        float tm0 = -INFINITY, tm1 = -INFINITY;
        #pragma unroll
        for (int jj = 0; jj < 32; jj++) {
            tm0 = fmaxf(tm0, s0[jj]);
            tm1 = fmaxf(tm1, s1[jj]);
        }
        const float mn0 = fmaxf(m0, tm0), mn1 = fmaxf(m1, tm1);
        const float sc0 = __expf(m0 - mn0), sc1 = __expf(m1 - mn1);
        float sum0 = 0.f, sum1 = 0.f;
        #pragma unroll
        for (int jj = 0; jj < 32; jj++) {
            const float p0 = __expf(s0[jj] - mn0);
            const float p1 = __expf(s1[jj] - mn1);
            s0[jj] = p0; s1[jj] = p1;
            sum0 += p0; sum1 += p1;
        }
        l0 = l0 * sc0 + sum0; m0 = mn0;
        l1 = l1 * sc1 + sum1; m1 = mn1;
        {
            const unsigned long long sc02 = pk2(sc0, sc0);
            const unsigned long long sc12 = pk2(sc1, sc1);
            #pragma unroll
            for (int u = 0; u < 8; u++) {
                o0[u] = mul2(o0[u], sc02);
                o1[u] = mul2(o1[u], sc12);
            }
        }

        #pragma unroll
        for (int jj = 0; jj < 32; jj++) {
            const unsigned long long p02 = pk2(s0[jj], s0[jj]);
            const unsigned long long p12 = pk2(s1[jj], s1[jj]);
            const unsigned long long* vp = (const unsigned long long*)&Vs[jj][qd * 16];
            #pragma unroll
            for (int u = 0; u < 8; u++) {
                const unsigned long long vv = vp[u];
                fma2(o0[u], p02, vv);
                fma2(o1[u], p12, vv);
            }
        }
    }

    const float inv0 = 1.f / l0, inv1 = 1.f / l1;
    const long yo = (long)(b * Tn + ia) * Cn + h * HDn + qd * 16;
    #pragma unroll
    for (int u = 0; u < 8; u++) {
        float2 e = up2(o0[u]);
        const float a0 = e.x * inv0, a1 = e.y * inv0;
        __nv_bfloat16 h0 = __float2bfloat16(a0), h1 = __float2bfloat16(a1);
        g_yh[yo + u * 2]     = h0;
        g_yh[yo + u * 2 + 1] = h1;
        g_yl[yo + u * 2]     = __float2bfloat16(a0 - __bfloat162float(h0));
        g_yl[yo + u * 2 + 1] = __float2bfloat16(a1 - __bfloat162float(h1));
    }
    #pragma unroll
    for (int u = 0; u < 8; u++) {
        float2 e = up2(o1[u]);
        const float a0 = e.x * inv1, a1 = e.y * inv1;
        __nv_bfloat16 h0 = __float2bfloat16(a0), h1 = __float2bfloat16(a1);
        g_yh[yo + Cn + u * 2]     = h0;
        g_yh[yo + Cn + u * 2 + 1] = h1;
        g_yl[yo + Cn + u * 2]     = __float2bfloat16(a0 - __bfloat162float(h0));
        g_yl[yo + Cn + u * 2 + 1] = __float2bfloat16(a1 - __bfloat162float(h1));
    }
}

// ============================================================================
extern "C" void kernel_launch(void* const* d_in, const int* in_sizes, int n_in,
                              void* d_out, int out_size)
{
    const float* x      = (const float*)d_in[0];
    const float* w_attn = (const float*)d_in[1];
    const float* b_attn = (const float*)d_in[2];
    const float* w_proj = (const float*)d_in[3];
    const float* b_proj = (const float*)d_in[4];
    const float* sel_w  = (const float*)d_in[5];
    float* out = (float*)d_out;

    __nv_bfloat16 *xh, *xl, *wah, *wal, *wph, *wpl, *qsh, *qsl, *kh, *kl, *yh, *yl;
    cudaGetSymbolAddress((void**)&xh,  g_xh);  cudaGetSymbolAddress((void**)&xl,  g_xl);
    cudaGetSymbolAddress((void**)&wah, g_wah); cudaGetSymbolAddress((void**)&wal, g_wal);
    cudaGetSymbolAddress((void**)&wph, g_wph); cudaGetSymbolAddress((void**)&wpl, g_wpl);
    cudaGetSymbolAddress((void**)&qsh, g_qsh); cudaGetSymbolAddress((void**)&qsl, g_qsl);
    cudaGetSymbolAddress((void**)&kh,  g_kh);  cudaGetSymbolAddress((void**)&kl,  g_kl);
    cudaGetSymbolAddress((void**)&yh,  g_yh);  cudaGetSymbolAddress((void**)&yl,  g_yl);

    // 0) bf16 hi/lo splits of inputs
    split_bf16<<<(Bn * Tn * Cn) / 256, 256>>>(x, xh, xl, Bn * Tn * Cn);
    split_bf16<<<(QKVn * Cn) / 256, 256>>>(w_attn, wah, wal, QKVn * Cn);
    split_bf16<<<(Cn * Cn) / 256, 256>>>(w_proj, wph, wpl, Cn * Cn);

    // 1) qkv = x @ w_attn^T + b_attn  (epilogue also splits scaled-q and k)
    gemm_mma<0><<<dim3(QKVn / 128, (Bn * Tn) / 128, 1), 256>>>(
        xh, xl, wah, wal, Cn, Cn, 0, 0, b_attn, sel_w, nullptr);

    // 2) S = relu(scale * qs @ k^T), masked
    gemm_mma<1><<<dim3(Tn / 128, Tn / 128, Bn), 256>>>(
        qsh, qsl, kh, kl, Cn, Cn, (long)Tn * Cn, (long)Tn * Cn,
        nullptr, nullptr, nullptr);

    // 3) FF_shifted = exclusive cumsum of S over rows
    cumsum_p1<<<(Bn * NSEG * Tn) / 256, 256>>>();
    cumsum_p2<<<(Bn * NSEG * Tn) / 256, 256>>>();

    // 4) attention with forgetting term (writes y as bf16 hi/lo)
    attn_kernel<<<dim3(Tn / 64, Bn * Hn), 128>>>();

    // 5) out = y @ w_proj^T + b_proj
    gemm_mma<2><<<dim3(Cn / 128, (Bn * Tn) / 128, 1), 256>>>(
        yh, yl, wph, wpl, Cn, Cn, 0, 0, b_proj, nullptr, out);
}

// round 9
// speedup vs baseline: 1.9156x; 1.5324x over previous
#include <cuda_runtime.h>
#include <cuda_bf16.h>
#include <math.h>
#include <stdint.h>

#define Bn   2
#define Tn   2048
#define Cn   768
#define Hn   12
#define HDn  64
#define QKVn 2304
#define SCALE 0.125f   // 1/sqrt(64)
#define NSEG 32        // cumsum segments (64 rows each)

// -------- device scratch (no allocations allowed) --------
__device__ float g_ff  [Bn * Tn * Tn];       // S, then exclusive cumsum
__device__ float g_part[Bn * NSEG * Tn];     // cumsum segment partials
__device__ __nv_bfloat16 g_xh [Bn*Tn*Cn], g_xl [Bn*Tn*Cn];
__device__ __nv_bfloat16 g_wah[QKVn*Cn],  g_wal[QKVn*Cn];
__device__ __nv_bfloat16 g_wph[Cn*Cn],    g_wpl[Cn*Cn];
__device__ __nv_bfloat16 g_qh [Bn*Tn*Cn], g_ql [Bn*Tn*Cn];  // raw q (attn)
__device__ __nv_bfloat16 g_qsh[Bn*Tn*Cn], g_qsl[Bn*Tn*Cn];  // sel_w-scaled q
__device__ __nv_bfloat16 g_kh [Bn*Tn*Cn], g_kl [Bn*Tn*Cn];
__device__ __nv_bfloat16 g_vh [Bn*Tn*Cn], g_vl [Bn*Tn*Cn];
__device__ __nv_bfloat16 g_yh [Bn*Tn*Cn], g_yl [Bn*Tn*Cn];

// ======================= PTX helpers (compute_103-safe) ====================
__device__ __forceinline__ uint32_t smem_u32(const void* p) {
    uint32_t a;
    asm("{ .reg .u64 t; cvta.to.shared.u64 t, %1; cvt.u32.u64 %0, t; }"
        : "=r"(a) : "l"(p));
    return a;
}
__device__ __forceinline__ void ldsm4(uint32_t* r, uint32_t addr) {
    asm volatile("ldmatrix.sync.aligned.m8n8.x4.shared.b16 {%0,%1,%2,%3}, [%4];"
                 : "=r"(r[0]), "=r"(r[1]), "=r"(r[2]), "=r"(r[3]) : "r"(addr));
}
__device__ __forceinline__ void ldsm4t(uint32_t* r, uint32_t addr) {
    asm volatile("ldmatrix.sync.aligned.m8n8.x4.trans.shared.b16 {%0,%1,%2,%3}, [%4];"
                 : "=r"(r[0]), "=r"(r[1]), "=r"(r[2]), "=r"(r[3]) : "r"(addr));
}
__device__ __forceinline__ void mma16816(float* c, const uint32_t* a, const uint32_t* b) {
    asm volatile(
        "mma.sync.aligned.m16n8k16.row.col.f32.bf16.bf16.f32 "
        "{%0,%1,%2,%3}, {%4,%5,%6,%7}, {%8,%9}, {%0,%1,%2,%3};"
        : "+f"(c[0]), "+f"(c[1]), "+f"(c[2]), "+f"(c[3])
        : "r"(a[0]), "r"(a[1]), "r"(a[2]), "r"(a[3]), "r"(b[0]), "r"(b[1]));
}
__device__ __forceinline__ void cpasync16(uint32_t dst, const void* src) {
    asm volatile("cp.async.cg.shared.global [%0], [%1], 16;" :: "r"(dst), "l"(src));
}

// ============================================================================
// bf16 split helper: src fp32 -> (hi, lo) bf16
// ============================================================================
__global__ void split_bf16(const float* __restrict__ src,
                           __nv_bfloat16* __restrict__ h,
                           __nv_bfloat16* __restrict__ l, int n)
{
    int i = blockIdx.x * 256 + threadIdx.x;
    if (i < n) {
        float v = src[i];
        __nv_bfloat16 hh = __float2bfloat16(v);
        h[i] = hh;
        l[i] = __float2bfloat16(v - __bfloat162float(hh));
    }
}

// ============================================================================
// bf16x3 tensor-core GEMM (HMMA): C[m,n]=sum_k A[m,k]*B[n,k]
// AhBh+AhBl+AlBh, fp32 accum. 128x128 block, BK=16, 8 warps, cp.async x2.
// MODE 0 qkv (bias + split-scatter q/qs/k/v) / 1 selection-S / 2 proj.
// ============================================================================
#define TILEB 6144          // 128 rows * 48 bytes
#define STAGEB (4 * TILEB)  // Ah, Al, Bh, Bl

template <int MODE>
__global__ void __launch_bounds__(256)
gemm_mma(const __nv_bfloat16* __restrict__ Ah, const __nv_bfloat16* __restrict__ Al,
         const __nv_bfloat16* __restrict__ Bh, const __nv_bfloat16* __restrict__ Bl,
         int lda, int ldb, long sA, long sB,
         const float* __restrict__ bias, const float* __restrict__ selw,
         float* __restrict__ Cout)
{
    const int i0 = blockIdx.y * 128, j0 = blockIdx.x * 128, bz = blockIdx.z;
    if (MODE == 1 && j0 > i0) return;        // strictly-upper tiles: zero, never read
    Ah += (long)bz * sA; Al += (long)bz * sA;
    Bh += (long)bz * sB; Bl += (long)bz * sB;

    __shared__ __align__(128) char sm[2 * STAGEB];   // 48 KB
    const uint32_t sb = smem_u32(sm);

    const int tid = threadIdx.x;
    const int lane = tid & 31, wid = tid >> 5;
    const int wm = (wid & 1) * 64, wn = (wid >> 1) * 32;

    const int lrow = tid >> 1, lhalf = tid & 1;
    const __nv_bfloat16* srcs[4] = {
        Ah + (long)(i0 + lrow) * lda + lhalf * 8,
        Al + (long)(i0 + lrow) * lda + lhalf * 8,
        Bh + (long)(j0 + lrow) * ldb + lhalf * 8,
        Bl + (long)(j0 + lrow) * ldb + lhalf * 8 };
    const uint32_t dstb = sb + lrow * 48 + lhalf * 16;

    uint32_t a_addr[4], b_addr[2];
    {
        const int r = wm + (lane & 15);
        const int c = (lane >> 4) * 16;
        #pragma unroll
        for (int mi = 0; mi < 4; mi++)
            a_addr[mi] = sb + (r + mi * 16) * 48 + c;
        const int n = wn + (lane & 7) + (lane >> 4) * 8;
        const int kc = ((lane >> 3) & 1) * 16;
        #pragma unroll
        for (int nc = 0; nc < 2; nc++)
            b_addr[nc] = sb + 2 * TILEB + (n + nc * 16) * 48 + kc;
    }

    float acc[4][4][4];
    #pragma unroll
    for (int mi = 0; mi < 4; mi++)
        #pragma unroll
        for (int ni = 0; ni < 4; ni++)
            #pragma unroll
            for (int e = 0; e < 4; e++) acc[mi][ni][e] = 0.f;

    const int NT = Cn / 16;    // 48
    auto load_stage = [&](int t) {
        const uint32_t off = (t & 1) * STAGEB;
        const int k0 = t * 16;
        #pragma unroll
        for (int m4 = 0; m4 < 4; m4++)
            cpasync16(dstb + off + m4 * TILEB, (const void*)(srcs[m4] + k0));
        asm volatile("cp.async.commit_group;");
    };

    load_stage(0);
    for (int t = 0; t < NT; t++) {
        if (t + 1 < NT) {
            load_stage(t + 1);
            asm volatile("cp.async.wait_group 1;");
        } else {
            asm volatile("cp.async.wait_group 0;");
        }
        __syncthreads();

        const uint32_t off = (t & 1) * STAGEB;
        uint32_t fah[4][4], fal[4][4], fbh[2][4], fbl[2][4];
        #pragma unroll
        for (int mi = 0; mi < 4; mi++) {
            ldsm4(fah[mi], a_addr[mi] + off);
            ldsm4(fal[mi], a_addr[mi] + off + TILEB);
        }
        #pragma unroll
        for (int nc = 0; nc < 2; nc++) {
            ldsm4(fbh[nc], b_addr[nc] + off);
            ldsm4(fbl[nc], b_addr[nc] + off + TILEB);
        }
        #pragma unroll
        for (int mi = 0; mi < 4; mi++)
            #pragma unroll
            for (int ni = 0; ni < 4; ni++) {
                const int nc = ni >> 1, sel = (ni & 1) * 2;
                mma16816(acc[mi][ni], fah[mi], &fbh[nc][sel]);
                mma16816(acc[mi][ni], fah[mi], &fbl[nc][sel]);
                mma16816(acc[mi][ni], fal[mi], &fbh[nc][sel]);
            }
        __syncthreads();
    }

    const int g = lane >> 2, t4 = lane & 3;
    #pragma unroll
    for (int mi = 0; mi < 4; mi++) {
        #pragma unroll
        for (int ni = 0; ni < 4; ni++) {
            const int col = j0 + wn + ni * 8 + t4 * 2;
            #pragma unroll
            for (int e = 0; e < 4; e++) {
                const int m = i0 + wm + mi * 16 + g + (e >> 1) * 8;
                const int n = col + (e & 1);
                const float raw = acc[mi][ni][e];
                if (MODE == 0) {
                    const float v = raw + bias[n];
                    if (n < Cn) {
                        const long ix = (long)m * Cn + n;
                        __nv_bfloat16 h = __float2bfloat16(v);
                        g_qh[ix] = h;
                        g_ql[ix] = __float2bfloat16(v - __bfloat162float(h));
                        const float qv = v * selw[n >> 6];
                        __nv_bfloat16 hs = __float2bfloat16(qv);
                        g_qsh[ix] = hs;
                        g_qsl[ix] = __float2bfloat16(qv - __bfloat162float(hs));
                    } else if (n < 2 * Cn) {
                        const long ix = (long)m * Cn + n - Cn;
                        __nv_bfloat16 h = __float2bfloat16(v);
                        g_kh[ix] = h;
                        g_kl[ix] = __float2bfloat16(v - __bfloat162float(h));
                    } else {
                        const long ix = (long)m * Cn + n - 2 * Cn;
                        __nv_bfloat16 h = __float2bfloat16(v);
                        g_vh[ix] = h;
                        g_vl[ix] = __float2bfloat16(v - __bfloat162float(h));
                    }
                } else if (MODE == 1) {
                    float v = raw * SCALE;
                    v = (n >= 1 && n < m) ? fmaxf(v, 0.f) : 0.f;
                    g_ff[(long)bz * Tn * Tn + (long)m * Tn + n] = v;
                } else {
                    Cout[(long)m * Cn + n] = raw + bias[n];
                }
            }
        }
    }
}

// ============================================================================
// Parallel exclusive cumsum of S over rows i (NSEG=32 segments of 64 rows)
// ============================================================================
__global__ void cumsum_p1()
{
    const int g = blockIdx.x * 256 + threadIdx.x;
    const int j = g & (Tn - 1);
    const int seg = (g >> 11) & (NSEG - 1);
    const int b = g >> 16;
    const float* col = g_ff + (long)b * Tn * Tn + j;
    const int ibeg = seg * (Tn / NSEG);
    float s = 0.f;
    #pragma unroll 8
    for (int k = 0; k < Tn / NSEG; k++) {
        const int i = ibeg + k;
        const float v = col[(long)i * Tn];
        if (i > j) s += v;
    }
    g_part[g] = s;
}

__global__ void cumsum_p2()
{
    const int g = blockIdx.x * 256 + threadIdx.x;
    const int j = g & (Tn - 1);
    const int seg = (g >> 11) & (NSEG - 1);
    const int b = g >> 16;
    const float* pp = g_part + (b << 16) + j;
    float acc = 0.f;
    for (int s2 = 0; s2 < seg; s2++) acc += pp[s2 << 11];
    float* col = g_ff + (long)b * Tn * Tn + j;
    const int ibeg = seg * (Tn / NSEG);
    #pragma unroll 8
    for (int k = 0; k < Tn / NSEG; k++) {
        const int i = ibeg + k;
        const float v = col[(long)i * Tn];
        col[(long)i * Tn] = acc;          // exclusive prefix (FF_shifted)
        if (i > j) acc += v;
    }
}

// ============================================================================
// Tensor-core flash attention with forgetting term.
// Block = (q tile of 128 rows) x (b,h). 8 warps, 16 rows each. KV tiles of 64.
// QK^T: 3-product bf16 split MMA; softmax on fp32 frags (FF from smem);
// P re-split to bf16 hi/lo in-register (C-frag == A-frag layout);
// PV: 3-product MMA with V via ldmatrix.trans. cp.async double buffer.
// ============================================================================
#define BR 128
#define BC 64
#define QTB 18432            // 128 * 144 B (one Q tile, bf16, pitch 72 halves)
#define KVB 9216             // 64 * 144 B
#define FTB 34816            // 128 * 272 B (F tile fp32, pitch 68 floats)
#define STG (4 * KVB + FTB)  // 71680
#define ATT_SMEM (2 * QTB + 2 * STG)   // 180224

__global__ void __launch_bounds__(256) attn_mma()
{
    const int bx = blockIdx.x, bh = blockIdx.y;
    const int b = bh / Hn, h = bh % Hn;
    const int tid = threadIdx.x, lane = tid & 31, wid = tid >> 5;
    const int i0 = bx * BR;

    extern __shared__ __align__(16) char sm[];
    const uint32_t sb = smem_u32(sm);

    const __nv_bfloat16* gq_h = g_qh + (long)(b * Tn + i0) * Cn + h * HDn;
    const __nv_bfloat16* gq_l = g_ql + (long)(b * Tn + i0) * Cn + h * HDn;
    const __nv_bfloat16* gk_h = g_kh + (long)b * Tn * Cn + h * HDn;
    const __nv_bfloat16* gk_l = g_kl + (long)b * Tn * Cn + h * HDn;
    const __nv_bfloat16* gv_h = g_vh + (long)b * Tn * Cn + h * HDn;
    const __nv_bfloat16* gv_l = g_vl + (long)b * Tn * Cn + h * HDn;
    const float* gf = g_ff + (long)b * Tn * Tn + (long)i0 * Tn;

    auto ld_tile = [&](int t) {
        const uint32_t st = sb + 2 * QTB + (t & 1) * STG;
        const int j0 = t * BC;
        const int r = tid >> 2;
        const int cb = (tid & 3) * 2;
        #pragma unroll
        for (int u = 0; u < 2; u++) {
            const int c = cb + u;
            const long so = (long)(j0 + r) * Cn + c * 8;
            const uint32_t d = st + r * 144 + c * 16;
            cpasync16(d,           gk_h + so);
            cpasync16(d + KVB,     gk_l + so);
            cpasync16(d + 2 * KVB, gv_h + so);
            cpasync16(d + 3 * KVB, gv_l + so);
        }
        const int r2 = tid >> 1;
        const int fb = (tid & 1) * 8;
        #pragma unroll
        for (int u = 0; u < 8; u++)
            cpasync16(st + 4 * KVB + r2 * 272 + (fb + u) * 16,
                      gf + (long)r2 * Tn + j0 + (fb + u) * 4);
        asm volatile("cp.async.commit_group;");
    };

    // Q tiles + tile 0 into group 0
    {
        const int r = tid >> 1, c0 = (tid & 1) * 4;
        #pragma unroll
        for (int u = 0; u < 4; u++) {
            const long so = (long)r * Cn + (c0 + u) * 8;
            cpasync16(sb + r * 144 + (c0 + u) * 16,       gq_h + so);
            cpasync16(sb + QTB + r * 144 + (c0 + u) * 16, gq_l + so);
        }
    }
    ld_tile(0);

    uint32_t qa_h[4][4], qa_l[4][4];
    float o[8][4];
    #pragma unroll
    for (int f = 0; f < 8; f++)
        #pragma unroll
        for (int e = 0; e < 4; e++) o[f][e] = 0.f;
    float mrow[2] = {-INFINITY, -INFINITY};
    float lrow[2] = {0.f, 0.f};

    const int g = lane >> 2, t4 = lane & 3;
    const int nt = 2 * bx + 2;

    for (int t = 0; t < nt; t++) {
        if (t + 1 < nt) {
            ld_tile(t + 1);
            asm volatile("cp.async.wait_group 1;");
        } else {
            asm volatile("cp.async.wait_group 0;");
        }
        __syncthreads();

        const uint32_t st = sb + 2 * QTB + (t & 1) * STG;
        const char* stp = sm + 2 * QTB + (t & 1) * STG;
        const int j0 = t * BC;

        if (t == 0) {   // Q fragments (once)
            #pragma unroll
            for (int dc = 0; dc < 4; dc++) {
                const uint32_t qa = sb + (wid * 16 + (lane & 15)) * 144
                                  + dc * 32 + (lane >> 4) * 16;
                ldsm4(qa_h[dc], qa);
                ldsm4(qa_l[dc], qa + QTB);
            }
        }

        const bool skip = (j0 > i0 + wid * 16 + 15);   // warp fully masked
        if (!skip) {
            // ---- S = Q K^T (3 products)
            float sfr[8][4];
            #pragma unroll
            for (int f = 0; f < 8; f++)
                #pragma unroll
                for (int e = 0; e < 4; e++) sfr[f][e] = 0.f;
            #pragma unroll
            for (int jg = 0; jg < 4; jg++) {
                uint32_t kbh[4][4], kbl[4][4];
                const uint32_t ka = st + (jg * 16 + (lane & 7) + (lane >> 4) * 8) * 144
                                  + ((lane >> 3) & 1) * 16;
                #pragma unroll
                for (int dc = 0; dc < 4; dc++) {
                    ldsm4(kbh[dc], ka + dc * 32);
                    ldsm4(kbl[dc], ka + dc * 32 + KVB);
                }
                #pragma unroll
                for (int dc = 0; dc < 4; dc++) {
                    mma16816(sfr[2 * jg],     qa_h[dc], &kbh[dc][0]);
                    mma16816(sfr[2 * jg],     qa_h[dc], &kbl[dc][0]);
                    mma16816(sfr[2 * jg],     qa_l[dc], &kbh[dc][0]);
                    mma16816(sfr[2 * jg + 1], qa_h[dc], &kbh[dc][2]);
                    mma16816(sfr[2 * jg + 1], qa_h[dc], &kbl[dc][2]);
                    mma16816(sfr[2 * jg + 1], qa_l[dc], &kbh[dc][2]);
                }
            }

            // ---- softmax with FF (per row-half)
            const bool domask = (t >= 2 * bx);
            #pragma unroll
            for (int half = 0; half < 2; half++) {
                const int irow = i0 + wid * 16 + g + half * 8;
                const char* fr = stp + 4 * KVB + (wid * 16 + g + half * 8) * 272;
                float vmax = -INFINITY;
                #pragma unroll
                for (int f = 0; f < 8; f++) {
                    const float2 fv = *(const float2*)(fr + (f * 8 + 2 * t4) * 4);
                    float s0 = sfr[f][2 * half]     * SCALE - fv.x;
                    float s1 = sfr[f][2 * half + 1] * SCALE - fv.y;
                    if (domask) {
                        const int j = j0 + f * 8 + 2 * t4;
                        if (j     > irow) s0 = -INFINITY;
                        if (j + 1 > irow) s1 = -INFINITY;
                    }
                    sfr[f][2 * half] = s0; sfr[f][2 * half + 1] = s1;
                    vmax = fmaxf(vmax, fmaxf(s0, s1));
                }
                vmax = fmaxf(vmax, __shfl_xor_sync(0xffffffffu, vmax, 1));
                vmax = fmaxf(vmax, __shfl_xor_sync(0xffffffffu, vmax, 2));
                const float mnew = fmaxf(mrow[half], vmax);
                const float scl = __expf(mrow[half] - mnew);
                mrow[half] = mnew;
                float ls = 0.f;
                #pragma unroll
                for (int f = 0; f < 8; f++) {
                    const float p0 = __expf(sfr[f][2 * half]     - mnew);
                    const float p1 = __expf(sfr[f][2 * half + 1] - mnew);
                    sfr[f][2 * half] = p0; sfr[f][2 * half + 1] = p1;
                    ls += p0 + p1;
                }
                lrow[half] = lrow[half] * scl + ls;
                #pragma unroll
                for (int f = 0; f < 8; f++) {
                    o[f][2 * half]     *= scl;
                    o[f][2 * half + 1] *= scl;
                }
            }

            // ---- P -> bf16 hi/lo A-fragments
            uint32_t pa_h[4][4], pa_l[4][4];
            #pragma unroll
            for (int jc = 0; jc < 4; jc++) {
                #pragma unroll
                for (int rr = 0; rr < 4; rr++) {
                    const int f = 2 * jc + (rr >> 1);
                    const int e = (rr & 1) * 2;
                    const float p0 = sfr[f][e], p1 = sfr[f][e + 1];
                    const __nv_bfloat16 h0 = __float2bfloat16(p0);
                    const __nv_bfloat16 h1 = __float2bfloat16(p1);
                    __nv_bfloat162 ph; ph.x = h0; ph.y = h1;
                    __nv_bfloat162 pl;
                    pl.x = __float2bfloat16(p0 - __bfloat162float(h0));
                    pl.y = __float2bfloat16(p1 - __bfloat162float(h1));
                    pa_h[jc][rr] = *(uint32_t*)&ph;
                    pa_l[jc][rr] = *(uint32_t*)&pl;
                }
            }

            // ---- O += P V (3 products), V via trans ldmatrix
            #pragma unroll
            for (int dg = 0; dg < 4; dg++) {
                uint32_t vbh[4][4], vbl[4][4];
                #pragma unroll
                for (int jc = 0; jc < 4; jc++) {
                    const uint32_t va = st + 2 * KVB
                        + (jc * 16 + (lane & 7) + ((lane >> 3) & 1) * 8) * 144
                        + dg * 32 + (lane >> 4) * 16;
                    ldsm4t(vbh[jc], va);
                    ldsm4t(vbl[jc], va + KVB);
                }
                #pragma unroll
                for (int jc = 0; jc < 4; jc++) {
                    mma16816(o[2 * dg],     pa_h[jc], &vbh[jc][0]);
                    mma16816(o[2 * dg],     pa_h[jc], &vbl[jc][0]);
                    mma16816(o[2 * dg],     pa_l[jc], &vbh[jc][0]);
                    mma16816(o[2 * dg + 1], pa_h[jc], &vbh[jc][2]);
                    mma16816(o[2 * dg + 1], pa_h[jc], &vbl[jc][2]);
                    mma16816(o[2 * dg + 1], pa_l[jc], &vbh[jc][2]);
                }
            }
        }
        __syncthreads();
    }

    // ---- normalize and store y as bf16 hi/lo
    #pragma unroll
    for (int half = 0; half < 2; half++) {
        lrow[half] += __shfl_xor_sync(0xffffffffu, lrow[half], 1);
        lrow[half] += __shfl_xor_sync(0xffffffffu, lrow[half], 2);
    }
    const float inv[2] = {1.f / lrow[0], 1.f / lrow[1]};
    #pragma unroll
    for (int half = 0; half < 2; half++) {
        const long row = (long)(b * Tn + i0 + wid * 16 + g + half * 8);
        #pragma unroll
        for (int f = 0; f < 8; f++) {
            const float a0 = o[f][2 * half]     * inv[half];
            const float a1 = o[f][2 * half + 1] * inv[half];
            const __nv_bfloat16 h0 = __float2bfloat16(a0);
            const __nv_bfloat16 h1 = __float2bfloat16(a1);
            __nv_bfloat162 yh; yh.x = h0; yh.y = h1;
            __nv_bfloat162 yl;
            yl.x = __float2bfloat16(a0 - __bfloat162float(h0));
            yl.y = __float2bfloat16(a1 - __bfloat162float(h1));
            const long off = row * Cn + h * HDn + f * 8 + 2 * t4;
            *(__nv_bfloat162*)(g_yh + off) = yh;
            *(__nv_bfloat162*)(g_yl + off) = yl;
        }
    }
}

// ============================================================================
extern "C" void kernel_launch(void* const* d_in, const int* in_sizes, int n_in,
                              void* d_out, int out_size)
{
    const float* x      = (const float*)d_in[0];
    const float* w_attn = (const float*)d_in[1];
    const float* b_attn = (const float*)d_in[2];
    const float* w_proj = (const float*)d_in[3];
    const float* b_proj = (const float*)d_in[4];
    const float* sel_w  = (const float*)d_in[5];
    float* out = (float*)d_out;

    __nv_bfloat16 *xh, *xl, *wah, *wal, *wph, *wpl, *qsh, *qsl, *kh, *kl, *yh, *yl;
    cudaGetSymbolAddress((void**)&xh,  g_xh);  cudaGetSymbolAddress((void**)&xl,  g_xl);
    cudaGetSymbolAddress((void**)&wah, g_wah); cudaGetSymbolAddress((void**)&wal, g_wal);
    cudaGetSymbolAddress((void**)&wph, g_wph); cudaGetSymbolAddress((void**)&wpl, g_wpl);
    cudaGetSymbolAddress((void**)&qsh, g_qsh); cudaGetSymbolAddress((void**)&qsl, g_qsl);
    cudaGetSymbolAddress((void**)&kh,  g_kh);  cudaGetSymbolAddress((void**)&kl,  g_kl);
    cudaGetSymbolAddress((void**)&yh,  g_yh);  cudaGetSymbolAddress((void**)&yl,  g_yl);

    static bool attr_done = false;
    if (!attr_done) {
        cudaFuncSetAttribute(attn_mma,
            cudaFuncAttributeMaxDynamicSharedMemorySize, ATT_SMEM);
        attr_done = true;
    }

    // 0) bf16 hi/lo splits of inputs
    split_bf16<<<(Bn * Tn * Cn) / 256, 256>>>(x, xh, xl, Bn * Tn * Cn);
    split_bf16<<<(QKVn * Cn) / 256, 256>>>(w_attn, wah, wal, QKVn * Cn);
    split_bf16<<<(Cn * Cn) / 256, 256>>>(w_proj, wph, wpl, Cn * Cn);

    // 1) qkv GEMM (epilogue splits q/qs/k/v into bf16 hi/lo buffers)
    gemm_mma<0><<<dim3(QKVn / 128, (Bn * Tn) / 128, 1), 256>>>(
        xh, xl, wah, wal, Cn, Cn, 0, 0, b_attn, sel_w, nullptr);

    // 2) S = relu(scale * qs @ k^T), masked
    gemm_mma<1><<<dim3(Tn / 128, Tn / 128, Bn), 256>>>(
        qsh, qsl, kh, kl, Cn, Cn, (long)Tn * Cn, (long)Tn * Cn,
        nullptr, nullptr, nullptr);

    // 3) FF_shifted = exclusive cumsum of S over rows
    cumsum_p1<<<(Bn * NSEG * Tn) / 256, 256>>>();
    cumsum_p2<<<(Bn * NSEG * Tn) / 256, 256>>>();

    // 4) tensor-core flash attention with forgetting term
    attn_mma<<<dim3(Tn / BR, Bn * Hn), 256, ATT_SMEM>>>();

    // 5) out = y @ w_proj^T + b_proj
    gemm_mma<2><<<dim3(Cn / 128, (Bn * Tn) / 128, 1), 256>>>(
        yh, yl, wph, wpl, Cn, Cn, 0, 0, b_proj, nullptr, out);
}

// round 11
// speedup vs baseline: 3.7321x; 1.9483x over previous
#include <cuda_runtime.h>
#include <cuda_bf16.h>
#include <math.h>
#include <stdint.h>

#define Bn   2
#define Tn   2048
#define Cn   768
#define Hn   12
#define HDn  64
#define QKVn 2304
#define SCALE 0.125f   // 1/sqrt(64)
#define NSEG 32        // cumsum segments (64 rows each)

// -------- device scratch (no allocations allowed) --------
__device__ float g_ff  [Bn * Tn * Tn];       // S, then exclusive cumsum
__device__ float g_part[Bn * NSEG * Tn];     // cumsum segment partials
__device__ __nv_bfloat16 g_xh [Bn*Tn*Cn], g_xl [Bn*Tn*Cn];
__device__ __nv_bfloat16 g_wah[QKVn*Cn],  g_wal[QKVn*Cn];
__device__ __nv_bfloat16 g_wph[Cn*Cn],    g_wpl[Cn*Cn];
__device__ __nv_bfloat16 g_qh [Bn*Tn*Cn], g_ql [Bn*Tn*Cn];  // raw q (attn)
__device__ __nv_bfloat16 g_qsh[Bn*Tn*Cn], g_qsl[Bn*Tn*Cn];  // sel_w-scaled q
__device__ __nv_bfloat16 g_kh [Bn*Tn*Cn], g_kl [Bn*Tn*Cn];
__device__ __nv_bfloat16 g_vh [Bn*Tn*Cn], g_vl [Bn*Tn*Cn];
__device__ __nv_bfloat16 g_yh [Bn*Tn*Cn], g_yl [Bn*Tn*Cn];

// ======================= PTX helpers (compute_103-safe) ====================
__device__ __forceinline__ uint32_t smem_u32(const void* p) {
    uint32_t a;
    asm("{ .reg .u64 t; cvta.to.shared.u64 t, %1; cvt.u32.u64 %0, t; }"
        : "=r"(a) : "l"(p));
    return a;
}
__device__ __forceinline__ void ldsm4(uint32_t* r, uint32_t addr) {
    asm volatile("ldmatrix.sync.aligned.m8n8.x4.shared.b16 {%0,%1,%2,%3}, [%4];"
                 : "=r"(r[0]), "=r"(r[1]), "=r"(r[2]), "=r"(r[3]) : "r"(addr));
}
__device__ __forceinline__ void ldsm4t(uint32_t* r, uint32_t addr) {
    asm volatile("ldmatrix.sync.aligned.m8n8.x4.trans.shared.b16 {%0,%1,%2,%3}, [%4];"
                 : "=r"(r[0]), "=r"(r[1]), "=r"(r[2]), "=r"(r[3]) : "r"(addr));
}
__device__ __forceinline__ void mma16816(float* c, const uint32_t* a, const uint32_t* b) {
    asm volatile(
        "mma.sync.aligned.m16n8k16.row.col.f32.bf16.bf16.f32 "
        "{%0,%1,%2,%3}, {%4,%5,%6,%7}, {%8,%9}, {%0,%1,%2,%3};"
        : "+f"(c[0]), "+f"(c[1]), "+f"(c[2]), "+f"(c[3])
        : "r"(a[0]), "r"(a[1]), "r"(a[2]), "r"(a[3]), "r"(b[0]), "r"(b[1]));
}
__device__ __forceinline__ void cpasync16(uint32_t dst, const void* src) {
    asm volatile("cp.async.cg.shared.global [%0], [%1], 16;" :: "r"(dst), "l"(src));
}
// pack (v0, v1) into hi bf16x2 + lo (residual) bf16x2
__device__ __forceinline__ void split2(float v0, float v1,
                                       __nv_bfloat162& hh, __nv_bfloat162& ll) {
    hh.x = __float2bfloat16(v0);
    hh.y = __float2bfloat16(v1);
    ll.x = __float2bfloat16(v0 - __bfloat162float(hh.x));
    ll.y = __float2bfloat16(v1 - __bfloat162float(hh.y));
}

// ============================================================================
// bf16 split helper: src fp32 -> (hi, lo) bf16
// ============================================================================
__global__ void split_bf16(const float* __restrict__ src,
                           __nv_bfloat16* __restrict__ h,
                           __nv_bfloat16* __restrict__ l, int n)
{
    int i = blockIdx.x * 256 + threadIdx.x;
    if (i < n) {
        float v = src[i];
        __nv_bfloat16 hh = __float2bfloat16(v);
        h[i] = hh;
        l[i] = __float2bfloat16(v - __bfloat162float(hh));
    }
}

// ============================================================================
// bf16x3 tensor-core GEMM (HMMA): C[m,n]=sum_k A[m,k]*B[n,k]
// AhBh+AhBl+AlBh, fp32 accum. 128x128 block, BK=16, 8 warps, cp.async x2.
// __launch_bounds__(256,2): regs<=128 -> 2 CTAs/SM.
// MODE 0 qkv (bias + split-scatter q/qs/k/v) / 1 selection-S / 2 proj.
// ============================================================================
#define TILEB 6144          // 128 rows * 48 bytes
#define STAGEB (4 * TILEB)  // Ah, Al, Bh, Bl

template <int MODE>
__global__ void __launch_bounds__(256, 2)
gemm_mma(const __nv_bfloat16* __restrict__ Ah, const __nv_bfloat16* __restrict__ Al,
         const __nv_bfloat16* __restrict__ Bh, const __nv_bfloat16* __restrict__ Bl,
         int lda, int ldb, long sA, long sB,
         const float* __restrict__ bias, const float* __restrict__ selw,
         float* __restrict__ Cout)
{
    const int i0 = blockIdx.y * 128, j0 = blockIdx.x * 128, bz = blockIdx.z;
    if (MODE == 1 && j0 > i0) return;        // strictly-upper tiles: zero, never read
    Ah += (long)bz * sA; Al += (long)bz * sA;
    Bh += (long)bz * sB; Bl += (long)bz * sB;

    __shared__ __align__(128) char sm[2 * STAGEB];   // 48 KB
    const uint32_t sb = smem_u32(sm);

    const int tid = threadIdx.x;
    const int lane = tid & 31, wid = tid >> 5;
    const int wm = (wid & 1) * 64, wn = (wid >> 1) * 32;

    const int lrow = tid >> 1, lhalf = tid & 1;
    const __nv_bfloat16* srcs[4] = {
        Ah + (long)(i0 + lrow) * lda + lhalf * 8,
        Al + (long)(i0 + lrow) * lda + lhalf * 8,
        Bh + (long)(j0 + lrow) * ldb + lhalf * 8,
        Bl + (long)(j0 + lrow) * ldb + lhalf * 8 };
    const uint32_t dstb = sb + lrow * 48 + lhalf * 16;

    uint32_t a_addr[4], b_addr[2];
    {
        const int r = wm + (lane & 15);
        const int c = (lane >> 4) * 16;
        #pragma unroll
        for (int mi = 0; mi < 4; mi++)
            a_addr[mi] = sb + (r + mi * 16) * 48 + c;
        const int n = wn + (lane & 7) + (lane >> 4) * 8;
        const int kc = ((lane >> 3) & 1) * 16;
        #pragma unroll
        for (int nc = 0; nc < 2; nc++)
            b_addr[nc] = sb + 2 * TILEB + (n + nc * 16) * 48 + kc;
    }

    float acc[4][4][4];
    #pragma unroll
    for (int mi = 0; mi < 4; mi++)
        #pragma unroll
        for (int ni = 0; ni < 4; ni++)
            #pragma unroll
            for (int e = 0; e < 4; e++) acc[mi][ni][e] = 0.f;

    const int NT = Cn / 16;    // 48
    auto load_stage = [&](int t) {
        const uint32_t off = (t & 1) * STAGEB;
        const int k0 = t * 16;
        #pragma unroll
        for (int m4 = 0; m4 < 4; m4++)
            cpasync16(dstb + off + m4 * TILEB, (const void*)(srcs[m4] + k0));
        asm volatile("cp.async.commit_group;");
    };

    load_stage(0);
    for (int t = 0; t < NT; t++) {
        if (t + 1 < NT) {
            load_stage(t + 1);
            asm volatile("cp.async.wait_group 1;");
        } else {
            asm volatile("cp.async.wait_group 0;");
        }
        __syncthreads();

        const uint32_t off = (t & 1) * STAGEB;
        uint32_t fah[4][4], fal[4][4], fbh[2][4], fbl[2][4];
        #pragma unroll
        for (int mi = 0; mi < 4; mi++) {
            ldsm4(fah[mi], a_addr[mi] + off);
            ldsm4(fal[mi], a_addr[mi] + off + TILEB);
        }
        #pragma unroll
        for (int nc = 0; nc < 2; nc++) {
            ldsm4(fbh[nc], b_addr[nc] + off);
            ldsm4(fbl[nc], b_addr[nc] + off + TILEB);
        }
        #pragma unroll
        for (int mi = 0; mi < 4; mi++)
            #pragma unroll
            for (int ni = 0; ni < 4; ni++) {
                const int nc = ni >> 1, sel = (ni & 1) * 2;
                mma16816(acc[mi][ni], fah[mi], &fbh[nc][sel]);
                mma16816(acc[mi][ni], fah[mi], &fbl[nc][sel]);
                mma16816(acc[mi][ni], fal[mi], &fbh[nc][sel]);
            }
        __syncthreads();
    }

    // ---- epilogue: vectorized pair stores (n, n+1 adjacent in each e-pair)
    const int g = lane >> 2, t4 = lane & 3;
    #pragma unroll
    for (int mi = 0; mi < 4; mi++) {
        #pragma unroll
        for (int ni = 0; ni < 4; ni++) {
            const int n = j0 + wn + ni * 8 + t4 * 2;
            #pragma unroll
            for (int hp = 0; hp < 2; hp++) {     // e-pairs (0,1) and (2,3)
                const int m = i0 + wm + mi * 16 + g + hp * 8;
                const float r0 = acc[mi][ni][2 * hp];
                const float r1 = acc[mi][ni][2 * hp + 1];
                if (MODE == 0) {
                    const float v0 = r0 + bias[n], v1 = r1 + bias[n + 1];
                    __nv_bfloat162 hh, ll;
                    if (n < Cn) {
                        const long ix = (long)m * Cn + n;
                        split2(v0, v1, hh, ll);
                        *(__nv_bfloat162*)(g_qh + ix) = hh;
                        *(__nv_bfloat162*)(g_ql + ix) = ll;
                        split2(v0 * selw[n >> 6], v1 * selw[(n + 1) >> 6], hh, ll);
                        *(__nv_bfloat162*)(g_qsh + ix) = hh;
                        *(__nv_bfloat162*)(g_qsl + ix) = ll;
                    } else if (n < 2 * Cn) {
                        const long ix = (long)m * Cn + n - Cn;
                        split2(v0, v1, hh, ll);
                        *(__nv_bfloat162*)(g_kh + ix) = hh;
                        *(__nv_bfloat162*)(g_kl + ix) = ll;
                    } else {
                        const long ix = (long)m * Cn + n - 2 * Cn;
                        split2(v0, v1, hh, ll);
                        *(__nv_bfloat162*)(g_vh + ix) = hh;
                        *(__nv_bfloat162*)(g_vl + ix) = ll;
                    }
                } else if (MODE == 1) {
                    float v0 = r0 * SCALE, v1 = r1 * SCALE;
                    v0 = (n     >= 1 && n     < m) ? fmaxf(v0, 0.f) : 0.f;
                    v1 = (n + 1 >= 1 && n + 1 < m) ? fmaxf(v1, 0.f) : 0.f;
                    *(float2*)(g_ff + (long)bz * Tn * Tn + (long)m * Tn + n)
                        = make_float2(v0, v1);
                } else {
                    *(float2*)(Cout + (long)m * Cn + n)
                        = make_float2(r0 + bias[n], r1 + bias[n + 1]);
                }
            }
        }
    }
}

// ============================================================================
// Parallel exclusive cumsum of S over rows i (NSEG=32 segments of 64 rows)
// ============================================================================
__global__ void cumsum_p1()
{
    const int g = blockIdx.x * 256 + threadIdx.x;
    const int j = g & (Tn - 1);
    const int seg = (g >> 11) & (NSEG - 1);
    const int b = g >> 16;
    const float* col = g_ff + (long)b * Tn * Tn + j;
    const int ibeg = seg * (Tn / NSEG);
    float s = 0.f;
    #pragma unroll 8
    for (int k = 0; k < Tn / NSEG; k++) {
        const int i = ibeg + k;
        const float v = col[(long)i * Tn];
        if (i > j) s += v;
    }
    g_part[g] = s;
}

__global__ void cumsum_p2()
{
    const int g = blockIdx.x * 256 + threadIdx.x;
    const int j = g & (Tn - 1);
    const int seg = (g >> 11) & (NSEG - 1);
    const int b = g >> 16;
    const float* pp = g_part + (b << 16) + j;
    float acc = 0.f;
    for (int s2 = 0; s2 < seg; s2++) acc += pp[s2 << 11];
    float* col = g_ff + (long)b * Tn * Tn + j;
    const int ibeg = seg * (Tn / NSEG);
    #pragma unroll 8
    for (int k = 0; k < Tn / NSEG; k++) {
        const int i = ibeg + k;
        const float v = col[(long)i * Tn];
        col[(long)i * Tn] = acc;          // exclusive prefix (FF_shifted)
        if (i > j) acc += v;
    }
}

// ============================================================================
// Tensor-core flash attention with forgetting term.
// Block = (q tile of 128 rows) x (b,h). 8 warps, 16 rows each. KV tiles of 64.
// QK^T: 3-product bf16 split MMA; FF loaded direct from gmem into regs
// (prefetched before the MMA block); P re-split to bf16 hi/lo in-register;
// PV: 3-product MMA with V via ldmatrix.trans. cp.async double buffer (K/V).
// ============================================================================
#define BR 128
#define BC 64
#define QTB 18432            // 128 * 144 B (one Q tile, bf16, pitch 72 halves)
#define KVB 9216             // 64 * 144 B
#define STG (4 * KVB)        // 36864
#define ATT_SMEM (2 * QTB + 2 * STG)   // 110592

__global__ void __launch_bounds__(256) attn_mma()
{
    const int bx = blockIdx.x, bh = blockIdx.y;
    const int b = bh / Hn, h = bh % Hn;
    const int tid = threadIdx.x, lane = tid & 31, wid = tid >> 5;
    const int i0 = bx * BR;

    extern __shared__ __align__(16) char sm[];
    const uint32_t sb = smem_u32(sm);

    const __nv_bfloat16* gq_h = g_qh + (long)(b * Tn + i0) * Cn + h * HDn;
    const __nv_bfloat16* gq_l = g_ql + (long)(b * Tn + i0) * Cn + h * HDn;
    const __nv_bfloat16* gk_h = g_kh + (long)b * Tn * Cn + h * HDn;
    const __nv_bfloat16* gk_l = g_kl + (long)b * Tn * Cn + h * HDn;
    const __nv_bfloat16* gv_h = g_vh + (long)b * Tn * Cn + h * HDn;
    const __nv_bfloat16* gv_l = g_vl + (long)b * Tn * Cn + h * HDn;
    const float* gf = g_ff + (long)b * Tn * Tn + (long)i0 * Tn;

    auto ld_tile = [&](int t) {
        const uint32_t st = sb + 2 * QTB + (t & 1) * STG;
        const int j0 = t * BC;
        const int r = tid >> 2;
        const int cb = (tid & 3) * 2;
        #pragma unroll
        for (int u = 0; u < 2; u++) {
            const int c = cb + u;
            const long so = (long)(j0 + r) * Cn + c * 8;
            const uint32_t d = st + r * 144 + c * 16;
            cpasync16(d,           gk_h + so);
            cpasync16(d + KVB,     gk_l + so);
            cpasync16(d + 2 * KVB, gv_h + so);
            cpasync16(d + 3 * KVB, gv_l + so);
        }
        asm volatile("cp.async.commit_group;");
    };

    // Q tiles + tile 0 into group 0
    {
        const int r = tid >> 1, c0 = (tid & 1) * 4;
        #pragma unroll
        for (int u = 0; u < 4; u++) {
            const long so = (long)r * Cn + (c0 + u) * 8;
            cpasync16(sb + r * 144 + (c0 + u) * 16,       gq_h + so);
            cpasync16(sb + QTB + r * 144 + (c0 + u) * 16, gq_l + so);
        }
    }
    ld_tile(0);

    uint32_t qa_h[4][4], qa_l[4][4];
    float o[8][4];
    #pragma unroll
    for (int f = 0; f < 8; f++)
        #pragma unroll
        for (int e = 0; e < 4; e++) o[f][e] = 0.f;
    float mrow[2] = {-INFINITY, -INFINITY};
    float lrow[2] = {0.f, 0.f};

    const int g = lane >> 2, t4 = lane & 3;
    const int nt = 2 * bx + 2;

    for (int t = 0; t < nt; t++) {
        if (t + 1 < nt) {
            ld_tile(t + 1);
            asm volatile("cp.async.wait_group 1;");
        } else {
            asm volatile("cp.async.wait_group 0;");
        }
        __syncthreads();

        const uint32_t st = sb + 2 * QTB + (t & 1) * STG;
        const int j0 = t * BC;

        if (t == 0) {   // Q fragments (once)
            #pragma unroll
            for (int dc = 0; dc < 4; dc++) {
                const uint32_t qa = sb + (wid * 16 + (lane & 15)) * 144
                                  + dc * 32 + (lane >> 4) * 16;
                ldsm4(qa_h[dc], qa);
                ldsm4(qa_l[dc], qa + QTB);
            }
        }

        const bool skip = (j0 > i0 + wid * 16 + 15);   // warp fully masked
        if (!skip) {
            // ---- prefetch FF pairs into regs (overlaps with MMA below)
            float2 fv[2][8];
            #pragma unroll
            for (int half = 0; half < 2; half++) {
                const float* fr = gf + (long)(wid * 16 + g + half * 8) * Tn
                                + j0 + 2 * t4;
                #pragma unroll
                for (int f = 0; f < 8; f++)
                    fv[half][f] = *(const float2*)(fr + f * 8);
            }

            // ---- S = Q K^T (3 products)
            float sfr[8][4];
            #pragma unroll
            for (int f = 0; f < 8; f++)
                #pragma unroll
                for (int e = 0; e < 4; e++) sfr[f][e] = 0.f;
            #pragma unroll
            for (int jg = 0; jg < 4; jg++) {
                uint32_t kbh[4][4], kbl[4][4];
                const uint32_t ka = st + (jg * 16 + (lane & 7) + (lane >> 4) * 8) * 144
                                  + ((lane >> 3) & 1) * 16;
                #pragma unroll
                for (int dc = 0; dc < 4; dc++) {
                    ldsm4(kbh[dc], ka + dc * 32);
                    ldsm4(kbl[dc], ka + dc * 32 + KVB);
                }
                #pragma unroll
                for (int dc = 0; dc < 4; dc++) {
                    mma16816(sfr[2 * jg],     qa_h[dc], &kbh[dc][0]);
                    mma16816(sfr[2 * jg],     qa_h[dc], &kbl[dc][0]);
                    mma16816(sfr[2 * jg],     qa_l[dc], &kbh[dc][0]);
                    mma16816(sfr[2 * jg + 1], qa_h[dc], &kbh[dc][2]);
                    mma16816(sfr[2 * jg + 1], qa_h[dc], &kbl[dc][2]);
                    mma16816(sfr[2 * jg + 1], qa_l[dc], &kbh[dc][2]);
                }
            }

            // ---- softmax with FF (per row-half)
            const bool domask = (t >= 2 * bx);
            #pragma unroll
            for (int half = 0; half < 2; half++) {
                const int irow = i0 + wid * 16 + g + half * 8;
                float vmax = -INFINITY;
                #pragma unroll
                for (int f = 0; f < 8; f++) {
                    float s0 = sfr[f][2 * half]     * SCALE - fv[half][f].x;
                    float s1 = sfr[f][2 * half + 1] * SCALE - fv[half][f].y;
                    if (domask) {
                        const int j = j0 + f * 8 + 2 * t4;
                        if (j     > irow) s0 = -INFINITY;
                        if (j + 1 > irow) s1 = -INFINITY;
                    }
                    sfr[f][2 * half] = s0; sfr[f][2 * half + 1] = s1;
                    vmax = fmaxf(vmax, fmaxf(s0, s1));
                }
                vmax = fmaxf(vmax, __shfl_xor_sync(0xffffffffu, vmax, 1));
                vmax = fmaxf(vmax, __shfl_xor_sync(0xffffffffu, vmax, 2));
                const float mnew = fmaxf(mrow[half], vmax);
                const float scl = __expf(mrow[half] - mnew);
                mrow[half] = mnew;
                float ls = 0.f;
                #pragma unroll
                for (int f = 0; f < 8; f++) {
                    const float p0 = __expf(sfr[f][2 * half]     - mnew);
                    const float p1 = __expf(sfr[f][2 * half + 1] - mnew);
                    sfr[f][2 * half] = p0; sfr[f][2 * half + 1] = p1;
                    ls += p0 + p1;
                }
                lrow[half] = lrow[half] * scl + ls;
                #pragma unroll
                for (int f = 0; f < 8; f++) {
                    o[f][2 * half]     *= scl;
                    o[f][2 * half + 1] *= scl;
                }
            }

            // ---- P -> bf16 hi/lo A-fragments
            uint32_t pa_h[4][4], pa_l[4][4];
            #pragma unroll
            for (int jc = 0; jc < 4; jc++) {
                #pragma unroll
                for (int rr = 0; rr < 4; rr++) {
                    const int f = 2 * jc + (rr >> 1);
                    const int e = (rr & 1) * 2;
                    __nv_bfloat162 ph, pl;
                    split2(sfr[f][e], sfr[f][e + 1], ph, pl);
                    pa_h[jc][rr] = *(uint32_t*)&ph;
                    pa_l[jc][rr] = *(uint32_t*)&pl;
                }
            }

            // ---- O += P V (3 products), V via trans ldmatrix
            #pragma unroll
            for (int dg = 0; dg < 4; dg++) {
                uint32_t vbh[4][4], vbl[4][4];
                #pragma unroll
                for (int jc = 0; jc < 4; jc++) {
                    const uint32_t va = st + 2 * KVB
                        + (jc * 16 + (lane & 7) + ((lane >> 3) & 1) * 8) * 144
                        + dg * 32 + (lane >> 4) * 16;
                    ldsm4t(vbh[jc], va);
                    ldsm4t(vbl[jc], va + KVB);
                }
                #pragma unroll
                for (int jc = 0; jc < 4; jc++) {
                    mma16816(o[2 * dg],     pa_h[jc], &vbh[jc][0]);
                    mma16816(o[2 * dg],     pa_h[jc], &vbl[jc][0]);
                    mma16816(o[2 * dg],     pa_l[jc], &vbh[jc][0]);
                    mma16816(o[2 * dg + 1], pa_h[jc], &vbh[jc][2]);
                    mma16816(o[2 * dg + 1], pa_h[jc], &vbl[jc][2]);
                    mma16816(o[2 * dg + 1], pa_l[jc], &vbh[jc][2]);
                }
            }
        }
        __syncthreads();
    }

    // ---- normalize and store y as bf16 hi/lo
    #pragma unroll
    for (int half = 0; half < 2; half++) {
        lrow[half] += __shfl_xor_sync(0xffffffffu, lrow[half], 1);
        lrow[half] += __shfl_xor_sync(0xffffffffu, lrow[half], 2);
    }
    const float inv[2] = {1.f / lrow[0], 1.f / lrow[1]};
    #pragma unroll
    for (int half = 0; half < 2; half++) {
        const long row = (long)(b * Tn + i0 + wid * 16 + g + half * 8);
        #pragma unroll
        for (int f = 0; f < 8; f++) {
            const float a0 = o[f][2 * half]     * inv[half];
            const float a1 = o[f][2 * half + 1] * inv[half];
            __nv_bfloat162 yh, yl;
            split2(a0, a1, yh, yl);
            const long off = row * Cn + h * HDn + f * 8 + 2 * t4;
            *(__nv_bfloat162*)(g_yh + off) = yh;
            *(__nv_bfloat162*)(g_yl + off) = yl;
        }
    }
}

// ============================================================================
extern "C" void kernel_launch(void* const* d_in, const int* in_sizes, int n_in,
                              void* d_out, int out_size)
{
    const float* x      = (const float*)d_in[0];
    const float* w_attn = (const float*)d_in[1];
    const float* b_attn = (const float*)d_in[2];
    const float* w_proj = (const float*)d_in[3];
    const float* b_proj = (const float*)d_in[4];
    const float* sel_w  = (const float*)d_in[5];
    float* out = (float*)d_out;

    __nv_bfloat16 *xh, *xl, *wah, *wal, *wph, *wpl, *qsh, *qsl, *kh, *kl, *yh, *yl;
    cudaGetSymbolAddress((void**)&xh,  g_xh);  cudaGetSymbolAddress((void**)&xl,  g_xl);
    cudaGetSymbolAddress((void**)&wah, g_wah); cudaGetSymbolAddress((void**)&wal, g_wal);
    cudaGetSymbolAddress((void**)&wph, g_wph); cudaGetSymbolAddress((void**)&wpl, g_wpl);
    cudaGetSymbolAddress((void**)&qsh, g_qsh); cudaGetSymbolAddress((void**)&qsl, g_qsl);
    cudaGetSymbolAddress((void**)&kh,  g_kh);  cudaGetSymbolAddress((void**)&kl,  g_kl);
    cudaGetSymbolAddress((void**)&yh,  g_yh);  cudaGetSymbolAddress((void**)&yl,  g_yl);

    static bool attr_done = false;
    if (!attr_done) {
        cudaFuncSetAttribute(attn_mma,
            cudaFuncAttributeMaxDynamicSharedMemorySize, ATT_SMEM);
        attr_done = true;
    }

    // 0) bf16 hi/lo splits of inputs
    split_bf16<<<(Bn * Tn * Cn) / 256, 256>>>(x, xh, xl, Bn * Tn * Cn);
    split_bf16<<<(QKVn * Cn) / 256, 256>>>(w_attn, wah, wal, QKVn * Cn);
    split_bf16<<<(Cn * Cn) / 256, 256>>>(w_proj, wph, wpl, Cn * Cn);

    // 1) qkv GEMM (epilogue splits q/qs/k/v into bf16 hi/lo buffers)
    gemm_mma<0><<<dim3(QKVn / 128, (Bn * Tn) / 128, 1), 256>>>(
        xh, xl, wah, wal, Cn, Cn, 0, 0, b_attn, sel_w, nullptr);

    // 2) S = relu(scale * qs @ k^T), masked
    gemm_mma<1><<<dim3(Tn / 128, Tn / 128, Bn), 256>>>(
        qsh, qsl, kh, kl, Cn, Cn, (long)Tn * Cn, (long)Tn * Cn,
        nullptr, nullptr, nullptr);

    // 3) FF_shifted = exclusive cumsum of S over rows
    cumsum_p1<<<(Bn * NSEG * Tn) / 256, 256>>>();
    cumsum_p2<<<(Bn * NSEG * Tn) / 256, 256>>>();

    // 4) tensor-core flash attention with forgetting term
    attn_mma<<<dim3(Tn / BR, Bn * Hn), 256, ATT_SMEM>>>();

    // 5) out = y @ w_proj^T + b_proj
    gemm_mma<2><<<dim3(Cn / 128, (Bn * Tn) / 128, 1), 256>>>(
        yh, yl, wph, wpl, Cn, Cn, 0, 0, b_proj, nullptr, out);
}